// round 13
// baseline (speedup 1.0000x reference)
#include <cuda_runtime.h>
#include <cuda_fp16.h>
#include <math.h>
#include <stdint.h>

#define NN     20000
#define INC    512
#define HID1   512      // H1*HID = 8*64
#define OUTC   256
#define NE     320000
#define NTOT   (NE + NN)   // edges + self loops = 340000
#define NEGS   0.2f
#define KDIM   512
#define CAP1   96
#define CAP2   128
#define SBLK   ((NN + 255) / 256)   // 79

// ---------------- scratch ----------------
__device__ __half g_h1[(size_t)NN * HID1];
__device__ __half g_h2[(size_t)NN * OUTC];
__device__ __half g_xs[(size_t)NN * KDIM];
__device__ __half g_o1s[(size_t)NN * KDIM];
__device__ __half g_w1t[(size_t)HID1 * KDIM];
__device__ __half g_w2t[(size_t)OUTC * KDIM];
__device__ float g_as1[NN * 8];
__device__ float g_ad1[NN * 8];
__device__ float g_as2[NN];
__device__ float g_ad2[NN];
__device__ int   g_deg[NN];      // zero at load; self-reset by scan2 each call
__device__ int   g_part[SBLK];
__device__ int   g_offs[NN + 1];
__device__ int   g_cursor[NN];
__device__ int   g_csr[NTOT];

// ---------------- helpers ----------------
__device__ __forceinline__ float warp_sum(float v) {
#pragma unroll
    for (int o = 16; o; o >>= 1) v += __shfl_xor_sync(0xffffffffu, v, o);
    return v;
}
__device__ __forceinline__ int warp_sum_i(int v) {
#pragma unroll
    for (int o = 16; o; o >>= 1) v += __shfl_xor_sync(0xffffffffu, v, o);
    return v;
}
__device__ __forceinline__ float warp_max(float v) {
#pragma unroll
    for (int o = 16; o; o >>= 1) v = fmaxf(v, __shfl_xor_sync(0xffffffffu, v, o));
    return v;
}
__device__ __forceinline__ unsigned fenc(float f) {
    unsigned u = __float_as_uint(f);
    return (u >> 31) ? ~u : (u | 0x80000000u);
}
__device__ __forceinline__ float fdec(unsigned u) {
    return __uint_as_float((u >> 31) ? (u & 0x7fffffffu) : ~u);
}
__device__ __forceinline__ float lrelu(float a) { return a > 0.f ? a : NEGS * a; }

__device__ __forceinline__ uint32_t smem_u32(const void* p) {
    return (uint32_t)__cvta_generic_to_shared(p);
}
__device__ __forceinline__ void ldsm_x4(uint32_t& r0, uint32_t& r1, uint32_t& r2, uint32_t& r3, uint32_t addr) {
    asm volatile("ldmatrix.sync.aligned.m8n8.x4.shared.b16 {%0,%1,%2,%3}, [%4];\n"
                 : "=r"(r0), "=r"(r1), "=r"(r2), "=r"(r3) : "r"(addr));
}
__device__ __forceinline__ void cp_async16(uint32_t dst, const void* src, bool pred) {
    int sz = pred ? 16 : 0;
    asm volatile("cp.async.cg.shared.global [%0], [%1], 16, %2;\n"
                 :: "r"(dst), "l"(src), "r"(sz));
}
__device__ __forceinline__ void cp_commit() {
    asm volatile("cp.async.commit_group;\n" ::: "memory");
}

// ---------------- CSR build ----------------
// histogram; also zeroes alpha2 accumulators (joins main stream before GEMM2)
__global__ void deg_kernel(const int* __restrict__ ei) {
    int i = blockIdx.x * blockDim.x + threadIdx.x;
    if (i < NN) { g_as2[i] = 0.f; g_ad2[i] = 0.f; }
    if (i < NTOT) {
        int d = (i < NE) ? ei[NE + i] : (i - NE);
        atomicAdd(&g_deg[d], 1);
    }
}
// per-block partial sums of degrees
__global__ void partsum_kernel() {
    __shared__ int ws[8];
    int b = blockIdx.x, tid = threadIdx.x;
    int i = b * 256 + tid;
    int v = (i < NN) ? g_deg[i] : 0;
    int r = warp_sum_i(v);
    if ((tid & 31) == 0) ws[tid >> 5] = r;
    __syncthreads();
    if (tid == 0) {
        int s = 0;
#pragma unroll
        for (int j = 0; j < 8; j++) s += ws[j];
        g_part[b] = s;
    }
}
// final scan: block offset from partials + local scan; self-resets g_deg
__global__ void scan2_kernel() {
    __shared__ int ws[8];
    __shared__ int ws2[8];
    __shared__ int s_off;
    int b = blockIdx.x, tid = threadIdx.x;
    int lane = tid & 31, w = tid >> 5;

    // offset = sum of partials before this block
    int pv = (tid < b && tid < SBLK) ? g_part[tid] : 0;
    int r = warp_sum_i(pv);
    if (lane == 0) ws[w] = r;
    __syncthreads();
    if (tid == 0) {
        int s = 0;
#pragma unroll
        for (int j = 0; j < 8; j++) s += ws[j];
        s_off = s;
    }

    int i = b * 256 + tid;
    int v = (i < NN) ? g_deg[i] : 0;
    if (i < NN) g_deg[i] = 0;
    // local inclusive scan
    int x = v;
#pragma unroll
    for (int o = 1; o < 32; o <<= 1) {
        int t = __shfl_up_sync(0xffffffffu, x, o);
        if (lane >= o) x += t;
    }
    if (lane == 31) ws2[w] = x;
    __syncthreads();
    int woff = 0;
#pragma unroll
    for (int j = 0; j < 8; j++) woff += (j < w) ? ws2[j] : 0;
    int incl = s_off + woff + x;
    if (i < NN) {
        g_offs[i + 1] = incl;
        g_cursor[i] = incl - v;
    }
    if (b == 0 && tid == 0) g_offs[0] = 0;
}
__global__ void scatter_kernel(const int* __restrict__ ei) {
    int i = blockIdx.x * blockDim.x + threadIdx.x;
    if (i < NTOT) {
        int s, d;
        if (i < NE) { s = ei[i]; d = ei[NE + i]; }
        else        { s = d = i - NE; }
        int p = atomicAdd(&g_cursor[d], 1);
        g_csr[p] = s;
    }
}

// ---------------- fp16 conversions ----------------
__global__ void conv_act_kernel(const float* __restrict__ in, __half* __restrict__ out, int M) {
    int idx = blockIdx.x * blockDim.x + threadIdx.x;
    int total = M * (KDIM / 4);
    if (idx >= total) return;
    int c4 = idx * 4;
    float4 v = *(const float4*)(in + c4);
    __half h0 = __float2half(v.x), h1 = __float2half(v.y);
    __half h2 = __float2half(v.z), h3 = __float2half(v.w);
    *(ushort4*)(out + c4) = make_ushort4(
        *(unsigned short*)&h0, *(unsigned short*)&h1,
        *(unsigned short*)&h2, *(unsigned short*)&h3);
}
__global__ void conv_w_kernel(const float* __restrict__ W1, const float* __restrict__ W2,
                              __half* __restrict__ w1t, __half* __restrict__ w2t) {
    int idx = blockIdx.x * blockDim.x + threadIdx.x;
    if (idx < KDIM * HID1) {
        int n = idx / KDIM, k = idx % KDIM;
        w1t[(size_t)n * KDIM + k] = __float2half(W1[(size_t)k * HID1 + n]);
    } else {
        int j = idx - KDIM * HID1;
        if (j < KDIM * OUTC) {
            int n = j / KDIM, k = j % KDIM;
            w2t[(size_t)n * KDIM + k] = __float2half(W2[(size_t)k * OUTC + n]);
        }
    }
}

// ---------------- fp16 tensor-core GEMM (NT), BK=64, 3-stage cp.async ----------------
#define BM 128
#define BN 128
#define BK 64
#define APAD 72
#define NSTAGE 3
#define GEMM_SMEM (NSTAGE * (BM + BN) * APAD * 2)   // 110592 bytes

__global__ __launch_bounds__(256, 2) void mma_gemm_kernel(
    const __half* __restrict__ A, const __half* __restrict__ Bt,
    __half* __restrict__ C, int M, int Nc, int K,
    const float* __restrict__ asrc, const float* __restrict__ adst,
    float* __restrict__ oas, float* __restrict__ oad, int heads)
{
    extern __shared__ __half sm[];
    const int STG = (BM + BN) * APAD;

    int tid = threadIdx.x;
    int warp = tid >> 5, lane = tid & 31;
    int wm = (warp & 3) * 32;
    int wn = (warp >> 2) * 64;
    int m0 = blockIdx.y * BM, n0 = blockIdx.x * BN;
    int g = lane >> 2, t4 = lane & 3;

    int a_row = (lane & 7) + ((lane >> 3) & 1) * 8;
    int a_half = (lane >> 4) * 8;
    int b_row = (lane & 7) + ((lane >> 4) << 3);
    int b_half = ((lane >> 3) & 1) * 8;

    int r0 = tid >> 3;
    int cq = (tid & 7) * 8;
    bool am[4];
#pragma unroll
    for (int i = 0; i < 4; i++) am[i] = (m0 + r0 + 32 * i) < M;
    const __half* gA = A + (size_t)(m0 + r0) * K + cq;
    const __half* gB = Bt + (size_t)(n0 + r0) * K + cq;

    float acc[2][8][4];
#pragma unroll
    for (int mi = 0; mi < 2; mi++)
#pragma unroll
        for (int ni = 0; ni < 8; ni++)
#pragma unroll
            for (int j = 0; j < 4; j++) acc[mi][ni][j] = 0.f;

    int nk = K / BK;   // 8

#define ISSUE(KT) {                                                               \
        int _buf = (KT) % NSTAGE;                                                 \
        int _k0 = (KT) * BK;                                                      \
        __half* sA = sm + _buf * STG;                                             \
        __half* sB = sA + BM * APAD;                                              \
        _Pragma("unroll")                                                         \
        for (int i = 0; i < 4; i++) {                                             \
            int rr = r0 + 32 * i;                                                 \
            cp_async16(smem_u32(sA + rr * APAD + cq), gA + (size_t)32 * i * K + _k0, am[i]); \
            cp_async16(smem_u32(sB + rr * APAD + cq), gB + (size_t)32 * i * K + _k0, true);  \
        }                                                                         \
        cp_commit();                                                              \
    }

    ISSUE(0);
    ISSUE(1);

    for (int kt = 0; kt < nk; kt++) {
        asm volatile("cp.async.wait_group 1;\n" ::: "memory");
        __syncthreads();
        if (kt + 2 < nk) { ISSUE(kt + 2); }
        else             { cp_commit(); }

        __half* sA = sm + (kt % NSTAGE) * STG;
        __half* sB = sA + BM * APAD;
#pragma unroll
        for (int kk = 0; kk < 4; kk++) {
            int kb = kk * 16;
            uint32_t af[2][4];
            uint32_t bfrag[8][2];
#pragma unroll
            for (int mi = 0; mi < 2; mi++) {
                uint32_t ad = smem_u32(sA + (wm + mi * 16 + a_row) * APAD + kb + a_half);
                ldsm_x4(af[mi][0], af[mi][1], af[mi][2], af[mi][3], ad);
            }
#pragma unroll
            for (int p = 0; p < 4; p++) {
                uint32_t bd = smem_u32(sB + (wn + p * 16 + b_row) * APAD + kb + b_half);
                ldsm_x4(bfrag[2 * p][0], bfrag[2 * p][1], bfrag[2 * p + 1][0], bfrag[2 * p + 1][1], bd);
            }
#pragma unroll
            for (int mi = 0; mi < 2; mi++)
#pragma unroll
                for (int ni = 0; ni < 8; ni++) {
                    asm volatile(
                        "mma.sync.aligned.m16n8k16.row.col.f32.f16.f16.f32 "
                        "{%0,%1,%2,%3}, {%4,%5,%6,%7}, {%8,%9}, {%0,%1,%2,%3};\n"
                        : "+f"(acc[mi][ni][0]), "+f"(acc[mi][ni][1]),
                          "+f"(acc[mi][ni][2]), "+f"(acc[mi][ni][3])
                        : "r"(af[mi][0]), "r"(af[mi][1]), "r"(af[mi][2]), "r"(af[mi][3]),
                          "r"(bfrag[ni][0]), "r"(bfrag[ni][1]));
                }
        }
    }
#undef ISSUE

#pragma unroll
    for (int mi = 0; mi < 2; mi++) {
        int r = m0 + wm + mi * 16;
#pragma unroll
        for (int ni = 0; ni < 8; ni++) {
            int c = n0 + wn + ni * 8 + 2 * t4;
            if (r + g < M) {
                __half2 v0 = __floats2half2_rn(acc[mi][ni][0], acc[mi][ni][1]);
                *(__half2*)(C + (size_t)(r + g) * Nc + c) = v0;
            }
            if (r + g + 8 < M) {
                __half2 v1 = __floats2half2_rn(acc[mi][ni][2], acc[mi][ni][3]);
                *(__half2*)(C + (size_t)(r + g + 8) * Nc + c) = v1;
            }
        }
    }

    if (asrc) {
#pragma unroll
        for (int mi = 0; mi < 2; mi++) {
            float s0 = 0.f, s1 = 0.f, d0 = 0.f, d1 = 0.f;
#pragma unroll
            for (int ni = 0; ni < 8; ni++) {
#pragma unroll
                for (int j = 0; j < 2; j++) {
                    int c = n0 + wn + ni * 8 + 2 * t4 + j;
                    float a_s = asrc[c], a_d = adst[c];
                    s0 += acc[mi][ni][j] * a_s;
                    d0 += acc[mi][ni][j] * a_d;
                    s1 += acc[mi][ni][j + 2] * a_s;
                    d1 += acc[mi][ni][j + 2] * a_d;
                }
            }
#pragma unroll
            for (int o = 1; o < 4; o <<= 1) {
                s0 += __shfl_xor_sync(0xffffffffu, s0, o);
                s1 += __shfl_xor_sync(0xffffffffu, s1, o);
                d0 += __shfl_xor_sync(0xffffffffu, d0, o);
                d1 += __shfl_xor_sync(0xffffffffu, d1, o);
            }
            if (t4 == 0) {
                int r0w = m0 + wm + mi * 16 + g;
                int r1w = r0w + 8;
                if (heads == 8) {
                    int head = (n0 + wn) >> 6;
                    if (r0w < M) { oas[r0w * 8 + head] = s0; oad[r0w * 8 + head] = d0; }
                    if (r1w < M) { oas[r1w * 8 + head] = s1; oad[r1w * 8 + head] = d1; }
                } else {
                    if (r0w < M) { atomicAdd(&oas[r0w], s0); atomicAdd(&oad[r0w], d0); }
                    if (r1w < M) { atomicAdd(&oas[r1w], s1); atomicAdd(&oad[r1w], d1); }
                }
            }
        }
    }
}

// ---------------- layer1 aggregation: 2-edge-parallel gather ----------------
__global__ void agg1_kernel(const float* __restrict__ bias) {
    int n = blockIdx.x;
    int tid = threadIdx.x;
    int beg = g_offs[n], end = g_offs[n + 1];
    int deg = end - beg;

    __shared__ float s_ad[8];
    __shared__ float s_max[8];
    __shared__ float s_inv[8];
    __shared__ int   s_src[CAP1];
    __shared__ float s_alpha[CAP1][9];
    __shared__ unsigned s_maxi[8];
    __shared__ float s_sum8[8];
    __shared__ float4 s_part[128];

    if (tid < 8) {
        s_ad[tid] = g_ad1[n * 8 + tid];
        s_maxi[tid] = 0x007FFFFFu;
        s_sum8[tid] = 0.f;
    }
    __syncthreads();

    if (deg <= CAP1) {
        // stage logits
        for (int base = 0; base < deg; base += 32) {
            int el = base + (tid >> 3), hh = tid & 7;
            if (el < deg) {
                int s = g_csr[beg + el];
                if (hh == 0) s_src[el] = s;
                s_alpha[el][hh] = lrelu(g_as1[s * 8 + hh] + s_ad[hh]);
            }
        }
        __syncthreads();
        // per-head softmax (warp h), single expf, coef in place
        {
            int h = tid >> 5, l = tid & 31;
            float m = -INFINITY;
            for (int e = l; e < deg; e += 32) m = fmaxf(m, s_alpha[e][h]);
            m = warp_max(m);
            float ssum = 0.f;
            for (int e = l; e < deg; e += 32) {
                float ex = __expf(s_alpha[e][h] - m);
                s_alpha[e][h] = ex;
                ssum += ex;
            }
            ssum = warp_sum(ssum);
            float inv = 1.f / (ssum + 1e-16f);
            for (int e = l; e < deg; e += 32) s_alpha[e][h] *= inv;
        }
        __syncthreads();
        // gather: two 128-lane halves process different edges; 4 ch/thread
        int lane128 = tid & 127;
        int epair = tid >> 7;
        int c4 = lane128 * 4;
        int hch = c4 >> 6;
        float4 acc4 = make_float4(0.f, 0.f, 0.f, 0.f);
        int e = epair;
        for (; e + 2 < deg; e += 4) {
            uint2 ra = *(const uint2*)(g_h1 + (size_t)s_src[e] * HID1 + c4);
            uint2 rb = *(const uint2*)(g_h1 + (size_t)s_src[e + 2] * HID1 + c4);
            float ka = s_alpha[e][hch], kb = s_alpha[e + 2][hch];
            float2 a0 = __half22float2(*(__half2*)&ra.x);
            float2 a1 = __half22float2(*(__half2*)&ra.y);
            float2 b0 = __half22float2(*(__half2*)&rb.x);
            float2 b1 = __half22float2(*(__half2*)&rb.y);
            acc4.x += a0.x * ka + b0.x * kb;
            acc4.y += a0.y * ka + b0.y * kb;
            acc4.z += a1.x * ka + b1.x * kb;
            acc4.w += a1.y * ka + b1.y * kb;
        }
        for (; e < deg; e += 2) {
            uint2 ra = *(const uint2*)(g_h1 + (size_t)s_src[e] * HID1 + c4);
            float ka = s_alpha[e][hch];
            float2 a0 = __half22float2(*(__half2*)&ra.x);
            float2 a1 = __half22float2(*(__half2*)&ra.y);
            acc4.x += a0.x * ka;
            acc4.y += a0.y * ka;
            acc4.z += a1.x * ka;
            acc4.w += a1.y * ka;
        }
        if (epair == 1) s_part[lane128] = acc4;
        __syncthreads();
        if (epair == 0) {
            float4 o = s_part[lane128];
            acc4.x += o.x; acc4.y += o.y; acc4.z += o.z; acc4.w += o.w;
            float4 bv = *(const float4*)(bias + c4);
            float v0 = acc4.x + bv.x, v1 = acc4.y + bv.y;
            float v2 = acc4.z + bv.z, v3 = acc4.w + bv.w;
            v0 = v0 > 0.f ? v0 : expm1f(v0);
            v1 = v1 > 0.f ? v1 : expm1f(v1);
            v2 = v2 > 0.f ? v2 : expm1f(v2);
            v3 = v3 > 0.f ? v3 : expm1f(v3);
            __half h0 = __float2half(v0), h1 = __float2half(v1);
            __half h2 = __float2half(v2), h3 = __float2half(v3);
            *(ushort4*)(g_o1s + (size_t)n * KDIM + c4) = make_ushort4(
                *(unsigned short*)&h0, *(unsigned short*)&h1,
                *(unsigned short*)&h2, *(unsigned short*)&h3);
        }
    } else {
        // generic fallback (2 ch/thread, chunked)
        int c = 2 * tid;
        int hch = c >> 6;
        float accx = 0.f, accy = 0.f;
        const float4* as4 = (const float4*)g_as1;
        float lmax[8];
#pragma unroll
        for (int h = 0; h < 8; h++) lmax[h] = -INFINITY;
        for (int e = beg + tid; e < end; e += 256) {
            int s = g_csr[e];
            float4 lo = as4[s * 2], hi = as4[s * 2 + 1];
            float av[8] = {lo.x, lo.y, lo.z, lo.w, hi.x, hi.y, hi.z, hi.w};
#pragma unroll
            for (int h = 0; h < 8; h++) lmax[h] = fmaxf(lmax[h], lrelu(av[h] + s_ad[h]));
        }
#pragma unroll
        for (int h = 0; h < 8; h++) atomicMax(&s_maxi[h], fenc(lmax[h]));
        __syncthreads();
        if (tid < 8) s_max[tid] = fdec(s_maxi[tid]);
        __syncthreads();
        float lsum[8];
#pragma unroll
        for (int h = 0; h < 8; h++) lsum[h] = 0.f;
        for (int e = beg + tid; e < end; e += 256) {
            int s = g_csr[e];
            float4 lo = as4[s * 2], hi = as4[s * 2 + 1];
            float av[8] = {lo.x, lo.y, lo.z, lo.w, hi.x, hi.y, hi.z, hi.w};
#pragma unroll
            for (int h = 0; h < 8; h++) lsum[h] += __expf(lrelu(av[h] + s_ad[h]) - s_max[h]);
        }
#pragma unroll
        for (int h = 0; h < 8; h++) atomicAdd(&s_sum8[h], lsum[h]);
        __syncthreads();
        if (tid < 8) s_inv[tid] = 1.f / (s_sum8[tid] + 1e-16f);
        __syncthreads();
        for (int cb = beg; cb < end; cb += 32) {
            int cn = end - cb; if (cn > 32) cn = 32;
            int el = tid >> 3, hh = tid & 7;
            if (el < cn) {
                int s = g_csr[cb + el];
                float a = lrelu(g_as1[s * 8 + hh] + s_ad[hh]);
                s_alpha[el][hh] = __expf(a - s_max[hh]) * s_inv[hh];
                if (hh == 0) s_src[el] = s;
            }
            __syncthreads();
            for (int e = 0; e < cn; e++) {
                float2 v = __half22float2(*(const __half2*)(g_h1 + (size_t)s_src[e] * HID1 + c));
                float kc = s_alpha[e][hch];
                accx += v.x * kc;
                accy += v.y * kc;
            }
            __syncthreads();
        }
        float2 bv = *(const float2*)(bias + c);
        float ox = accx + bv.x, oy = accy + bv.y;
        ox = ox > 0.f ? ox : expm1f(ox);
        oy = oy > 0.f ? oy : expm1f(oy);
        __half hx = __float2half(ox), hy = __float2half(oy);
        *(ushort2*)(g_o1s + (size_t)n * KDIM + c) =
            make_ushort2(*(unsigned short*)&hx, *(unsigned short*)&hy);
    }
}

// ---------------- layer2 aggregation: single-expf softmax + log-softmax ----------------
__global__ void agg2_kernel(const float* __restrict__ bias, float* __restrict__ out) {
    int n = blockIdx.x;
    int tid = threadIdx.x;
    int beg = g_offs[n], end = g_offs[n + 1];
    int deg = end - beg;

    __shared__ float s_ad;
    __shared__ float s_max;
    __shared__ float s_inv;
    __shared__ unsigned s_maxi;
    __shared__ float s_sum1;
    __shared__ int   s_src[CAP2];
    __shared__ float s_alpha[CAP2];
    __shared__ float shm[8];
    __shared__ float shs[8];

    if (tid == 0) {
        s_ad = g_ad2[n];
        s_maxi = 0x007FFFFFu;
        s_sum1 = 0.f;
    }
    __syncthreads();

    float acc = 0.f;

    if (deg <= CAP2) {
        if (tid < deg) {
            int s = g_csr[beg + tid];
            s_src[tid] = s;
            s_alpha[tid] = lrelu(g_as2[s] + s_ad);
        }
        __syncthreads();
        if (tid < 32) {
            float m = -INFINITY;
            for (int e = tid; e < deg; e += 32) m = fmaxf(m, s_alpha[e]);
            m = warp_max(m);
            float ssum = 0.f;
            for (int e = tid; e < deg; e += 32) {
                float ex = __expf(s_alpha[e] - m);
                s_alpha[e] = ex;
                ssum += ex;
            }
            ssum = warp_sum(ssum);
            float inv = 1.f / (ssum + 1e-16f);
            for (int e = tid; e < deg; e += 32) s_alpha[e] *= inv;
        }
        __syncthreads();
        int e = 0;
        for (; e + 4 <= deg; e += 4) {
            float v0 = __half2float(g_h2[(size_t)s_src[e + 0] * OUTC + tid]);
            float v1 = __half2float(g_h2[(size_t)s_src[e + 1] * OUTC + tid]);
            float v2 = __half2float(g_h2[(size_t)s_src[e + 2] * OUTC + tid]);
            float v3 = __half2float(g_h2[(size_t)s_src[e + 3] * OUTC + tid]);
            acc += v0 * s_alpha[e + 0] + v1 * s_alpha[e + 1] + v2 * s_alpha[e + 2] + v3 * s_alpha[e + 3];
        }
        for (; e < deg; e++) acc += __half2float(g_h2[(size_t)s_src[e] * OUTC + tid]) * s_alpha[e];
    } else {
        float lmax = -INFINITY;
        for (int e = beg + tid; e < end; e += 256) {
            float a = lrelu(g_as2[g_csr[e]] + s_ad);
            lmax = fmaxf(lmax, a);
        }
        atomicMax(&s_maxi, fenc(lmax));
        __syncthreads();
        if (tid == 0) s_max = fdec(s_maxi);
        __syncthreads();
        float lsum = 0.f;
        for (int e = beg + tid; e < end; e += 256) {
            float a = lrelu(g_as2[g_csr[e]] + s_ad);
            lsum += __expf(a - s_max);
        }
        atomicAdd(&s_sum1, lsum);
        __syncthreads();
        if (tid == 0) s_inv = 1.f / (s_sum1 + 1e-16f);
        __syncthreads();
        for (int cb = beg; cb < end; cb += CAP2) {
            int cn = end - cb; if (cn > CAP2) cn = CAP2;
            if (tid < cn) {
                int s = g_csr[cb + tid];
                float a = lrelu(g_as2[s] + s_ad);
                s_alpha[tid] = __expf(a - s_max) * s_inv;
                s_src[tid] = s;
            }
            __syncthreads();
            for (int e = 0; e < cn; e++)
                acc += __half2float(g_h2[(size_t)s_src[e] * OUTC + tid]) * s_alpha[e];
            __syncthreads();
        }
    }

    float v = acc + bias[tid];
    float wm = warp_max(v);
    if ((tid & 31) == 0) shm[tid >> 5] = wm;
    __syncthreads();
    float m = shm[0];
#pragma unroll
    for (int i = 1; i < 8; i++) m = fmaxf(m, shm[i]);
    float ex = __expf(v - m);
    float ws = warp_sum(ex);
    if ((tid & 31) == 0) shs[tid >> 5] = ws;
    __syncthreads();
    float s = 0.f;
#pragma unroll
    for (int i = 0; i < 8; i++) s += shs[i];
    out[(size_t)n * OUTC + tid] = v - m - __logf(s);
}

// ---------------- launch (fork/join: CSR chain overlaps conv+GEMM1) ----------------
extern "C" void kernel_launch(void* const* d_in, const int* in_sizes, int n_in,
                              void* d_out, int out_size) {
    const float* x    = (const float*)d_in[0];
    const int*   ei   = (const int*)d_in[1];
    const float* W1   = (const float*)d_in[2];
    const float* as1  = (const float*)d_in[3];
    const float* ad1  = (const float*)d_in[4];
    const float* b1   = (const float*)d_in[5];
    const float* W2   = (const float*)d_in[6];
    const float* as2  = (const float*)d_in[7];
    const float* ad2  = (const float*)d_in[8];
    const float* b2   = (const float*)d_in[9];
    float* out = (float*)d_out;

    float *p_as1, *p_ad1, *p_as2, *p_ad2;
    __half *p_h1, *p_h2, *p_xs, *p_o1s, *p_w1t, *p_w2t;
    cudaGetSymbolAddress((void**)&p_h1, g_h1);
    cudaGetSymbolAddress((void**)&p_h2, g_h2);
    cudaGetSymbolAddress((void**)&p_as1, g_as1);
    cudaGetSymbolAddress((void**)&p_ad1, g_ad1);
    cudaGetSymbolAddress((void**)&p_as2, g_as2);
    cudaGetSymbolAddress((void**)&p_ad2, g_ad2);
    cudaGetSymbolAddress((void**)&p_xs, g_xs);
    cudaGetSymbolAddress((void**)&p_o1s, g_o1s);
    cudaGetSymbolAddress((void**)&p_w1t, g_w1t);
    cudaGetSymbolAddress((void**)&p_w2t, g_w2t);

    cudaFuncSetAttribute(mma_gemm_kernel,
                         cudaFuncAttributeMaxDynamicSharedMemorySize, GEMM_SMEM);

    static cudaStream_t s_side = nullptr;
    static cudaEvent_t ev_root = nullptr, ev_csr = nullptr;
    if (!s_side) {
        cudaStreamCreateWithFlags(&s_side, cudaStreamNonBlocking);
        cudaEventCreateWithFlags(&ev_root, cudaEventDisableTiming);
        cudaEventCreateWithFlags(&ev_csr, cudaEventDisableTiming);
    }

    // main stream: converts + GEMM1 (launches 1-3)
    conv_act_kernel<<<(NN * (KDIM / 4) + 255) / 256, 256>>>(x, p_xs, NN);
    conv_w_kernel<<<(KDIM * (HID1 + OUTC) + 255) / 256, 256>>>(W1, W2, p_w1t, p_w2t);
    cudaEventRecord(ev_root, 0);
    mma_gemm_kernel<<<dim3(HID1 / BN, (NN + BM - 1) / BM), 256, GEMM_SMEM>>>(
        p_xs, p_w1t, p_h1, NN, HID1, KDIM, as1, ad1, p_as1, p_ad1, 8);

    // side stream: CSR chain (launches 4-7; #4 = deg profiled)
    cudaStreamWaitEvent(s_side, ev_root, 0);
    deg_kernel<<<(NTOT + 255) / 256, 256, 0, s_side>>>(ei);
    partsum_kernel<<<SBLK, 256, 0, s_side>>>();
    scan2_kernel<<<SBLK, 256, 0, s_side>>>();
    scatter_kernel<<<(NTOT + 255) / 256, 256, 0, s_side>>>(ei);
    cudaEventRecord(ev_csr, s_side);

    // join: agg1 needs CSR + GEMM1
    cudaStreamWaitEvent(0, ev_csr, 0);
    agg1_kernel<<<NN, 256>>>(b1);

    // layer2 GEMM + fused alpha2
    mma_gemm_kernel<<<dim3(OUTC / BN, (NN + BM - 1) / BM), 256, GEMM_SMEM>>>(
        p_o1s, p_w2t, p_h2, NN, OUTC, KDIM, as2, ad2, p_as2, p_ad2, 1);

    // layer2 aggregation + log-softmax
    agg2_kernel<<<NN, 256>>>(b2, out);
}

// round 14
// speedup vs baseline: 1.6492x; 1.6492x over previous
#include <cuda_runtime.h>
#include <cuda_fp16.h>
#include <math.h>
#include <stdint.h>

#define NN     20000
#define INC    512
#define HID1   512      // H1*HID = 8*64
#define OUTC   256
#define NE     320000
#define NTOT   (NE + NN)   // edges + self loops = 340000
#define NEGS   0.2f
#define KDIM   512
#define CAP1   96
#define CAP2   128

// ---------------- scratch ----------------
__device__ __half g_h1[(size_t)NN * HID1];
__device__ __half g_h2[(size_t)NN * OUTC];
__device__ __half g_xs[(size_t)NN * KDIM];
__device__ __half g_o1s[(size_t)NN * KDIM];
__device__ __half g_w1t[(size_t)HID1 * KDIM];
__device__ __half g_w2t[(size_t)OUTC * KDIM];
__device__ float g_as1[NN * 8];
__device__ float g_ad1[NN * 8];
__device__ float g_as2[NN];
__device__ float g_ad2[NN];
__device__ int   g_deg[NN];      // zero at load; self-reset by scan each call
__device__ int   g_offs[NN + 1];
__device__ int   g_cursor[NN];
__device__ int   g_csr[NTOT];

// ---------------- helpers ----------------
__device__ __forceinline__ float warp_sum(float v) {
#pragma unroll
    for (int o = 16; o; o >>= 1) v += __shfl_xor_sync(0xffffffffu, v, o);
    return v;
}
__device__ __forceinline__ float warp_max(float v) {
#pragma unroll
    for (int o = 16; o; o >>= 1) v = fmaxf(v, __shfl_xor_sync(0xffffffffu, v, o));
    return v;
}
__device__ __forceinline__ unsigned fenc(float f) {
    unsigned u = __float_as_uint(f);
    return (u >> 31) ? ~u : (u | 0x80000000u);
}
__device__ __forceinline__ float fdec(unsigned u) {
    return __uint_as_float((u >> 31) ? (u & 0x7fffffffu) : ~u);
}
__device__ __forceinline__ float lrelu(float a) { return a > 0.f ? a : NEGS * a; }

__device__ __forceinline__ uint32_t smem_u32(const void* p) {
    return (uint32_t)__cvta_generic_to_shared(p);
}
__device__ __forceinline__ void ldsm_x4(uint32_t& r0, uint32_t& r1, uint32_t& r2, uint32_t& r3, uint32_t addr) {
    asm volatile("ldmatrix.sync.aligned.m8n8.x4.shared.b16 {%0,%1,%2,%3}, [%4];\n"
                 : "=r"(r0), "=r"(r1), "=r"(r2), "=r"(r3) : "r"(addr));
}
__device__ __forceinline__ void cp_async16(uint32_t dst, const void* src, bool pred) {
    int sz = pred ? 16 : 0;
    asm volatile("cp.async.cg.shared.global [%0], [%1], 16, %2;\n"
                 :: "r"(dst), "l"(src), "r"(sz));
}
__device__ __forceinline__ void cp_commit() {
    asm volatile("cp.async.commit_group;\n" ::: "memory");
}

// ---------------- CSR build ----------------
// histogram; also zeroes alpha2 accumulators (joins main stream before GEMM2)
__global__ void deg_kernel(const int* __restrict__ ei) {
    int i = blockIdx.x * blockDim.x + threadIdx.x;
    if (i < NN) { g_as2[i] = 0.f; g_ad2[i] = 0.f; }
    if (i < NTOT) {
        int d = (i < NE) ? ei[NE + i] : (i - NE);
        atomicAdd(&g_deg[d], 1);
    }
}
// scan; self-resets g_deg to zero for the next call
__global__ void scan_kernel() {
    __shared__ int warpsum[32];
    __shared__ int carry;
    int tid = threadIdx.x, lane = tid & 31, w = tid >> 5;
    if (tid == 0) { carry = 0; g_offs[0] = 0; }
    __syncthreads();
    for (int base = 0; base < NN; base += 1024) {
        int i = base + tid;
        int v = (i < NN) ? g_deg[i] : 0;
        if (i < NN) g_deg[i] = 0;
        int x = v;
#pragma unroll
        for (int o = 1; o < 32; o <<= 1) {
            int t = __shfl_up_sync(0xffffffffu, x, o);
            if (lane >= o) x += t;
        }
        if (lane == 31) warpsum[w] = x;
        __syncthreads();
        if (w == 0) {
            int s = warpsum[lane];
#pragma unroll
            for (int o = 1; o < 32; o <<= 1) {
                int t = __shfl_up_sync(0xffffffffu, s, o);
                if (lane >= o) s += t;
            }
            warpsum[lane] = s;
        }
        __syncthreads();
        int incl = carry + (w ? warpsum[w - 1] : 0) + x;
        if (i < NN) {
            g_offs[i + 1] = incl;
            g_cursor[i] = incl - v;
        }
        __syncthreads();
        if (tid == 1023) carry = incl;
        __syncthreads();
    }
}
__global__ void scatter_kernel(const int* __restrict__ ei) {
    int i = blockIdx.x * blockDim.x + threadIdx.x;
    if (i < NTOT) {
        int s, d;
        if (i < NE) { s = ei[i]; d = ei[NE + i]; }
        else        { s = d = i - NE; }
        int p = atomicAdd(&g_cursor[d], 1);
        g_csr[p] = s;
    }
}

// ---------------- fp16 conversions ----------------
__global__ void conv_act_kernel(const float* __restrict__ in, __half* __restrict__ out, int M) {
    int idx = blockIdx.x * blockDim.x + threadIdx.x;
    int total = M * (KDIM / 4);
    if (idx >= total) return;
    int c4 = idx * 4;
    float4 v = *(const float4*)(in + c4);
    __half h0 = __float2half(v.x), h1 = __float2half(v.y);
    __half h2 = __float2half(v.z), h3 = __float2half(v.w);
    *(ushort4*)(out + c4) = make_ushort4(
        *(unsigned short*)&h0, *(unsigned short*)&h1,
        *(unsigned short*)&h2, *(unsigned short*)&h3);
}
__global__ void conv_w_kernel(const float* __restrict__ W1, const float* __restrict__ W2,
                              __half* __restrict__ w1t, __half* __restrict__ w2t) {
    int idx = blockIdx.x * blockDim.x + threadIdx.x;
    if (idx < KDIM * HID1) {
        int n = idx / KDIM, k = idx % KDIM;
        w1t[(size_t)n * KDIM + k] = __float2half(W1[(size_t)k * HID1 + n]);
    } else {
        int j = idx - KDIM * HID1;
        if (j < KDIM * OUTC) {
            int n = j / KDIM, k = j % KDIM;
            w2t[(size_t)n * KDIM + k] = __float2half(W2[(size_t)k * OUTC + n]);
        }
    }
}

// ---------------- fp16 tensor-core GEMM (NT), BK=64, 3-stage cp.async ----------------
#define BM 128
#define BN 128
#define BK 64
#define APAD 72
#define NSTAGE 3
#define GEMM_SMEM (NSTAGE * (BM + BN) * APAD * 2)   // 110592 bytes

__global__ __launch_bounds__(256, 2) void mma_gemm_kernel(
    const __half* __restrict__ A, const __half* __restrict__ Bt,
    __half* __restrict__ C, int M, int Nc, int K,
    const float* __restrict__ asrc, const float* __restrict__ adst,
    float* __restrict__ oas, float* __restrict__ oad, int heads)
{
    extern __shared__ __half sm[];
    const int STG = (BM + BN) * APAD;

    int tid = threadIdx.x;
    int warp = tid >> 5, lane = tid & 31;
    int wm = (warp & 3) * 32;
    int wn = (warp >> 2) * 64;
    int m0 = blockIdx.y * BM, n0 = blockIdx.x * BN;
    int g = lane >> 2, t4 = lane & 3;

    int a_row = (lane & 7) + ((lane >> 3) & 1) * 8;
    int a_half = (lane >> 4) * 8;
    int b_row = (lane & 7) + ((lane >> 4) << 3);
    int b_half = ((lane >> 3) & 1) * 8;

    int r0 = tid >> 3;
    int cq = (tid & 7) * 8;
    bool am[4];
#pragma unroll
    for (int i = 0; i < 4; i++) am[i] = (m0 + r0 + 32 * i) < M;
    const __half* gA = A + (size_t)(m0 + r0) * K + cq;
    const __half* gB = Bt + (size_t)(n0 + r0) * K + cq;

    float acc[2][8][4];
#pragma unroll
    for (int mi = 0; mi < 2; mi++)
#pragma unroll
        for (int ni = 0; ni < 8; ni++)
#pragma unroll
            for (int j = 0; j < 4; j++) acc[mi][ni][j] = 0.f;

    int nk = K / BK;   // 8

#define ISSUE(KT) {                                                               \
        int _buf = (KT) % NSTAGE;                                                 \
        int _k0 = (KT) * BK;                                                      \
        __half* sA = sm + _buf * STG;                                             \
        __half* sB = sA + BM * APAD;                                              \
        _Pragma("unroll")                                                         \
        for (int i = 0; i < 4; i++) {                                             \
            int rr = r0 + 32 * i;                                                 \
            cp_async16(smem_u32(sA + rr * APAD + cq), gA + (size_t)32 * i * K + _k0, am[i]); \
            cp_async16(smem_u32(sB + rr * APAD + cq), gB + (size_t)32 * i * K + _k0, true);  \
        }                                                                         \
        cp_commit();                                                              \
    }

    ISSUE(0);
    ISSUE(1);

    for (int kt = 0; kt < nk; kt++) {
        asm volatile("cp.async.wait_group 1;\n" ::: "memory");
        __syncthreads();
        if (kt + 2 < nk) { ISSUE(kt + 2); }
        else             { cp_commit(); }

        __half* sA = sm + (kt % NSTAGE) * STG;
        __half* sB = sA + BM * APAD;
#pragma unroll
        for (int kk = 0; kk < 4; kk++) {
            int kb = kk * 16;
            uint32_t af[2][4];
            uint32_t bfrag[8][2];
#pragma unroll
            for (int mi = 0; mi < 2; mi++) {
                uint32_t ad = smem_u32(sA + (wm + mi * 16 + a_row) * APAD + kb + a_half);
                ldsm_x4(af[mi][0], af[mi][1], af[mi][2], af[mi][3], ad);
            }
#pragma unroll
            for (int p = 0; p < 4; p++) {
                uint32_t bd = smem_u32(sB + (wn + p * 16 + b_row) * APAD + kb + b_half);
                ldsm_x4(bfrag[2 * p][0], bfrag[2 * p][1], bfrag[2 * p + 1][0], bfrag[2 * p + 1][1], bd);
            }
#pragma unroll
            for (int mi = 0; mi < 2; mi++)
#pragma unroll
                for (int ni = 0; ni < 8; ni++) {
                    asm volatile(
                        "mma.sync.aligned.m16n8k16.row.col.f32.f16.f16.f32 "
                        "{%0,%1,%2,%3}, {%4,%5,%6,%7}, {%8,%9}, {%0,%1,%2,%3};\n"
                        : "+f"(acc[mi][ni][0]), "+f"(acc[mi][ni][1]),
                          "+f"(acc[mi][ni][2]), "+f"(acc[mi][ni][3])
                        : "r"(af[mi][0]), "r"(af[mi][1]), "r"(af[mi][2]), "r"(af[mi][3]),
                          "r"(bfrag[ni][0]), "r"(bfrag[ni][1]));
                }
        }
    }
#undef ISSUE

#pragma unroll
    for (int mi = 0; mi < 2; mi++) {
        int r = m0 + wm + mi * 16;
#pragma unroll
        for (int ni = 0; ni < 8; ni++) {
            int c = n0 + wn + ni * 8 + 2 * t4;
            if (r + g < M) {
                __half2 v0 = __floats2half2_rn(acc[mi][ni][0], acc[mi][ni][1]);
                *(__half2*)(C + (size_t)(r + g) * Nc + c) = v0;
            }
            if (r + g + 8 < M) {
                __half2 v1 = __floats2half2_rn(acc[mi][ni][2], acc[mi][ni][3]);
                *(__half2*)(C + (size_t)(r + g + 8) * Nc + c) = v1;
            }
        }
    }

    if (asrc) {
#pragma unroll
        for (int mi = 0; mi < 2; mi++) {
            float s0 = 0.f, s1 = 0.f, d0 = 0.f, d1 = 0.f;
#pragma unroll
            for (int ni = 0; ni < 8; ni++) {
#pragma unroll
                for (int j = 0; j < 2; j++) {
                    int c = n0 + wn + ni * 8 + 2 * t4 + j;
                    float a_s = asrc[c], a_d = adst[c];
                    s0 += acc[mi][ni][j] * a_s;
                    d0 += acc[mi][ni][j] * a_d;
                    s1 += acc[mi][ni][j + 2] * a_s;
                    d1 += acc[mi][ni][j + 2] * a_d;
                }
            }
#pragma unroll
            for (int o = 1; o < 4; o <<= 1) {
                s0 += __shfl_xor_sync(0xffffffffu, s0, o);
                s1 += __shfl_xor_sync(0xffffffffu, s1, o);
                d0 += __shfl_xor_sync(0xffffffffu, d0, o);
                d1 += __shfl_xor_sync(0xffffffffu, d1, o);
            }
            if (t4 == 0) {
                int r0w = m0 + wm + mi * 16 + g;
                int r1w = r0w + 8;
                if (heads == 8) {
                    int head = (n0 + wn) >> 6;
                    if (r0w < M) { oas[r0w * 8 + head] = s0; oad[r0w * 8 + head] = d0; }
                    if (r1w < M) { oas[r1w * 8 + head] = s1; oad[r1w * 8 + head] = d1; }
                } else {
                    if (r0w < M) { atomicAdd(&oas[r0w], s0); atomicAdd(&oad[r0w], d0); }
                    if (r1w < M) { atomicAdd(&oas[r1w], s1); atomicAdd(&oad[r1w], d1); }
                }
            }
        }
    }
}

// ---------------- layer1 aggregation: single-expf softmax + fp16 gather (unroll 8) ----------------
__global__ void agg1_kernel(const float* __restrict__ bias) {
    int n = blockIdx.x;
    int tid = threadIdx.x;
    int beg = g_offs[n], end = g_offs[n + 1];
    int deg = end - beg;

    __shared__ float s_ad[8];
    __shared__ float s_max[8];
    __shared__ float s_inv[8];
    __shared__ int   s_src[CAP1];
    __shared__ float s_alpha[CAP1][9];
    __shared__ unsigned s_maxi[8];
    __shared__ float s_sum8[8];

    if (tid < 8) {
        s_ad[tid] = g_ad1[n * 8 + tid];
        s_maxi[tid] = 0x007FFFFFu;
        s_sum8[tid] = 0.f;
    }
    __syncthreads();

    int c = 2 * tid;
    int hch = c >> 6;
    float accx = 0.f, accy = 0.f;

    if (deg <= CAP1) {
        for (int base = 0; base < deg; base += 32) {
            int el = base + (tid >> 3), hh = tid & 7;
            if (el < deg) {
                int s = g_csr[beg + el];
                if (hh == 0) s_src[el] = s;
                s_alpha[el][hh] = lrelu(g_as1[s * 8 + hh] + s_ad[hh]);
            }
        }
        __syncthreads();
        {
            int h = tid >> 5, l = tid & 31;
            float m = -INFINITY;
            for (int e = l; e < deg; e += 32) m = fmaxf(m, s_alpha[e][h]);
            m = warp_max(m);
            float ssum = 0.f;
            for (int e = l; e < deg; e += 32) {
                float ex = __expf(s_alpha[e][h] - m);
                s_alpha[e][h] = ex;
                ssum += ex;
            }
            ssum = warp_sum(ssum);
            float inv = 1.f / (ssum + 1e-16f);
            for (int e = l; e < deg; e += 32) s_alpha[e][h] *= inv;
        }
        __syncthreads();
        int e = 0;
        for (; e + 8 <= deg; e += 8) {
            float2 v0 = __half22float2(*(const __half2*)(g_h1 + (size_t)s_src[e + 0] * HID1 + c));
            float2 v1 = __half22float2(*(const __half2*)(g_h1 + (size_t)s_src[e + 1] * HID1 + c));
            float2 v2 = __half22float2(*(const __half2*)(g_h1 + (size_t)s_src[e + 2] * HID1 + c));
            float2 v3 = __half22float2(*(const __half2*)(g_h1 + (size_t)s_src[e + 3] * HID1 + c));
            float2 v4 = __half22float2(*(const __half2*)(g_h1 + (size_t)s_src[e + 4] * HID1 + c));
            float2 v5 = __half22float2(*(const __half2*)(g_h1 + (size_t)s_src[e + 5] * HID1 + c));
            float2 v6 = __half22float2(*(const __half2*)(g_h1 + (size_t)s_src[e + 6] * HID1 + c));
            float2 v7 = __half22float2(*(const __half2*)(g_h1 + (size_t)s_src[e + 7] * HID1 + c));
            float k0 = s_alpha[e + 0][hch], k1 = s_alpha[e + 1][hch];
            float k2 = s_alpha[e + 2][hch], k3 = s_alpha[e + 3][hch];
            float k4 = s_alpha[e + 4][hch], k5 = s_alpha[e + 5][hch];
            float k6 = s_alpha[e + 6][hch], k7 = s_alpha[e + 7][hch];
            accx += v0.x * k0 + v1.x * k1 + v2.x * k2 + v3.x * k3
                  + v4.x * k4 + v5.x * k5 + v6.x * k6 + v7.x * k7;
            accy += v0.y * k0 + v1.y * k1 + v2.y * k2 + v3.y * k3
                  + v4.y * k4 + v5.y * k5 + v6.y * k6 + v7.y * k7;
        }
        for (; e + 4 <= deg; e += 4) {
            float2 v0 = __half22float2(*(const __half2*)(g_h1 + (size_t)s_src[e + 0] * HID1 + c));
            float2 v1 = __half22float2(*(const __half2*)(g_h1 + (size_t)s_src[e + 1] * HID1 + c));
            float2 v2 = __half22float2(*(const __half2*)(g_h1 + (size_t)s_src[e + 2] * HID1 + c));
            float2 v3 = __half22float2(*(const __half2*)(g_h1 + (size_t)s_src[e + 3] * HID1 + c));
            float k0 = s_alpha[e + 0][hch], k1 = s_alpha[e + 1][hch];
            float k2 = s_alpha[e + 2][hch], k3 = s_alpha[e + 3][hch];
            accx += v0.x * k0 + v1.x * k1 + v2.x * k2 + v3.x * k3;
            accy += v0.y * k0 + v1.y * k1 + v2.y * k2 + v3.y * k3;
        }
        for (; e < deg; e++) {
            float2 v = __half22float2(*(const __half2*)(g_h1 + (size_t)s_src[e] * HID1 + c));
            float kc = s_alpha[e][hch];
            accx += v.x * kc;
            accy += v.y * kc;
        }
    } else {
        const float4* as4 = (const float4*)g_as1;
        float lmax[8];
#pragma unroll
        for (int h = 0; h < 8; h++) lmax[h] = -INFINITY;
        for (int e = beg + tid; e < end; e += 256) {
            int s = g_csr[e];
            float4 lo = as4[s * 2], hi = as4[s * 2 + 1];
            float av[8] = {lo.x, lo.y, lo.z, lo.w, hi.x, hi.y, hi.z, hi.w};
#pragma unroll
            for (int h = 0; h < 8; h++) lmax[h] = fmaxf(lmax[h], lrelu(av[h] + s_ad[h]));
        }
#pragma unroll
        for (int h = 0; h < 8; h++) atomicMax(&s_maxi[h], fenc(lmax[h]));
        __syncthreads();
        if (tid < 8) s_max[tid] = fdec(s_maxi[tid]);
        __syncthreads();
        float lsum[8];
#pragma unroll
        for (int h = 0; h < 8; h++) lsum[h] = 0.f;
        for (int e = beg + tid; e < end; e += 256) {
            int s = g_csr[e];
            float4 lo = as4[s * 2], hi = as4[s * 2 + 1];
            float av[8] = {lo.x, lo.y, lo.z, lo.w, hi.x, hi.y, hi.z, hi.w};
#pragma unroll
            for (int h = 0; h < 8; h++) lsum[h] += __expf(lrelu(av[h] + s_ad[h]) - s_max[h]);
        }
#pragma unroll
        for (int h = 0; h < 8; h++) atomicAdd(&s_sum8[h], lsum[h]);
        __syncthreads();
        if (tid < 8) s_inv[tid] = 1.f / (s_sum8[tid] + 1e-16f);
        __syncthreads();
        for (int cb = beg; cb < end; cb += 32) {
            int cn = end - cb; if (cn > 32) cn = 32;
            int el = tid >> 3, hh = tid & 7;
            if (el < cn) {
                int s = g_csr[cb + el];
                float a = lrelu(g_as1[s * 8 + hh] + s_ad[hh]);
                s_alpha[el][hh] = __expf(a - s_max[hh]) * s_inv[hh];
                if (hh == 0) s_src[el] = s;
            }
            __syncthreads();
            for (int e = 0; e < cn; e++) {
                float2 v = __half22float2(*(const __half2*)(g_h1 + (size_t)s_src[e] * HID1 + c));
                float kc = s_alpha[e][hch];
                accx += v.x * kc;
                accy += v.y * kc;
            }
            __syncthreads();
        }
    }

    float2 bv = *(const float2*)(bias + c);
    float ox = accx + bv.x, oy = accy + bv.y;
    ox = ox > 0.f ? ox : expm1f(ox);
    oy = oy > 0.f ? oy : expm1f(oy);
    __half hx = __float2half(ox), hy = __float2half(oy);
    *(ushort2*)(g_o1s + (size_t)n * KDIM + c) =
        make_ushort2(*(unsigned short*)&hx, *(unsigned short*)&hy);
}

// ---------------- layer2 aggregation: single-expf softmax + log-softmax (unroll 8) ----------------
__global__ void agg2_kernel(const float* __restrict__ bias, float* __restrict__ out) {
    int n = blockIdx.x;
    int tid = threadIdx.x;
    int beg = g_offs[n], end = g_offs[n + 1];
    int deg = end - beg;

    __shared__ float s_ad;
    __shared__ float s_max;
    __shared__ float s_inv;
    __shared__ unsigned s_maxi;
    __shared__ float s_sum1;
    __shared__ int   s_src[CAP2];
    __shared__ float s_alpha[CAP2];
    __shared__ float shm[8];
    __shared__ float shs[8];

    if (tid == 0) {
        s_ad = g_ad2[n];
        s_maxi = 0x007FFFFFu;
        s_sum1 = 0.f;
    }
    __syncthreads();

    float acc = 0.f;

    if (deg <= CAP2) {
        if (tid < deg) {
            int s = g_csr[beg + tid];
            s_src[tid] = s;
            s_alpha[tid] = lrelu(g_as2[s] + s_ad);
        }
        __syncthreads();
        if (tid < 32) {
            float m = -INFINITY;
            for (int e = tid; e < deg; e += 32) m = fmaxf(m, s_alpha[e]);
            m = warp_max(m);
            float ssum = 0.f;
            for (int e = tid; e < deg; e += 32) {
                float ex = __expf(s_alpha[e] - m);
                s_alpha[e] = ex;
                ssum += ex;
            }
            ssum = warp_sum(ssum);
            float inv = 1.f / (ssum + 1e-16f);
            for (int e = tid; e < deg; e += 32) s_alpha[e] *= inv;
        }
        __syncthreads();
        int e = 0;
        for (; e + 8 <= deg; e += 8) {
            float v0 = __half2float(g_h2[(size_t)s_src[e + 0] * OUTC + tid]);
            float v1 = __half2float(g_h2[(size_t)s_src[e + 1] * OUTC + tid]);
            float v2 = __half2float(g_h2[(size_t)s_src[e + 2] * OUTC + tid]);
            float v3 = __half2float(g_h2[(size_t)s_src[e + 3] * OUTC + tid]);
            float v4 = __half2float(g_h2[(size_t)s_src[e + 4] * OUTC + tid]);
            float v5 = __half2float(g_h2[(size_t)s_src[e + 5] * OUTC + tid]);
            float v6 = __half2float(g_h2[(size_t)s_src[e + 6] * OUTC + tid]);
            float v7 = __half2float(g_h2[(size_t)s_src[e + 7] * OUTC + tid]);
            acc += v0 * s_alpha[e + 0] + v1 * s_alpha[e + 1] + v2 * s_alpha[e + 2] + v3 * s_alpha[e + 3]
                 + v4 * s_alpha[e + 4] + v5 * s_alpha[e + 5] + v6 * s_alpha[e + 6] + v7 * s_alpha[e + 7];
        }
        for (; e + 4 <= deg; e += 4) {
            float v0 = __half2float(g_h2[(size_t)s_src[e + 0] * OUTC + tid]);
            float v1 = __half2float(g_h2[(size_t)s_src[e + 1] * OUTC + tid]);
            float v2 = __half2float(g_h2[(size_t)s_src[e + 2] * OUTC + tid]);
            float v3 = __half2float(g_h2[(size_t)s_src[e + 3] * OUTC + tid]);
            acc += v0 * s_alpha[e + 0] + v1 * s_alpha[e + 1] + v2 * s_alpha[e + 2] + v3 * s_alpha[e + 3];
        }
        for (; e < deg; e++) acc += __half2float(g_h2[(size_t)s_src[e] * OUTC + tid]) * s_alpha[e];
    } else {
        float lmax = -INFINITY;
        for (int e = beg + tid; e < end; e += 256) {
            float a = lrelu(g_as2[g_csr[e]] + s_ad);
            lmax = fmaxf(lmax, a);
        }
        atomicMax(&s_maxi, fenc(lmax));
        __syncthreads();
        if (tid == 0) s_max = fdec(s_maxi);
        __syncthreads();
        float lsum = 0.f;
        for (int e = beg + tid; e < end; e += 256) {
            float a = lrelu(g_as2[g_csr[e]] + s_ad);
            lsum += __expf(a - s_max);
        }
        atomicAdd(&s_sum1, lsum);
        __syncthreads();
        if (tid == 0) s_inv = 1.f / (s_sum1 + 1e-16f);
        __syncthreads();
        for (int cb = beg; cb < end; cb += CAP2) {
            int cn = end - cb; if (cn > CAP2) cn = CAP2;
            if (tid < cn) {
                int s = g_csr[cb + tid];
                float a = lrelu(g_as2[s] + s_ad);
                s_alpha[tid] = __expf(a - s_max) * s_inv;
                s_src[tid] = s;
            }
            __syncthreads();
            for (int e = 0; e < cn; e++)
                acc += __half2float(g_h2[(size_t)s_src[e] * OUTC + tid]) * s_alpha[e];
            __syncthreads();
        }
    }

    float v = acc + bias[tid];
    float wm = warp_max(v);
    if ((tid & 31) == 0) shm[tid >> 5] = wm;
    __syncthreads();
    float m = shm[0];
#pragma unroll
    for (int i = 1; i < 8; i++) m = fmaxf(m, shm[i]);
    float ex = __expf(v - m);
    float ws = warp_sum(ex);
    if ((tid & 31) == 0) shs[tid >> 5] = ws;
    __syncthreads();
    float s = 0.f;
#pragma unroll
    for (int i = 0; i < 8; i++) s += shs[i];
    out[(size_t)n * OUTC + tid] = v - m - __logf(s);
}

// ---------------- launch (fork/join: CSR chain overlaps conv+GEMM1) ----------------
extern "C" void kernel_launch(void* const* d_in, const int* in_sizes, int n_in,
                              void* d_out, int out_size) {
    const float* x    = (const float*)d_in[0];
    const int*   ei   = (const int*)d_in[1];
    const float* W1   = (const float*)d_in[2];
    const float* as1  = (const float*)d_in[3];
    const float* ad1  = (const float*)d_in[4];
    const float* b1   = (const float*)d_in[5];
    const float* W2   = (const float*)d_in[6];
    const float* as2  = (const float*)d_in[7];
    const float* ad2  = (const float*)d_in[8];
    const float* b2   = (const float*)d_in[9];
    float* out = (float*)d_out;

    float *p_as1, *p_ad1, *p_as2, *p_ad2;
    __half *p_h1, *p_h2, *p_xs, *p_o1s, *p_w1t, *p_w2t;
    cudaGetSymbolAddress((void**)&p_h1, g_h1);
    cudaGetSymbolAddress((void**)&p_h2, g_h2);
    cudaGetSymbolAddress((void**)&p_as1, g_as1);
    cudaGetSymbolAddress((void**)&p_ad1, g_ad1);
    cudaGetSymbolAddress((void**)&p_as2, g_as2);
    cudaGetSymbolAddress((void**)&p_ad2, g_ad2);
    cudaGetSymbolAddress((void**)&p_xs, g_xs);
    cudaGetSymbolAddress((void**)&p_o1s, g_o1s);
    cudaGetSymbolAddress((void**)&p_w1t, g_w1t);
    cudaGetSymbolAddress((void**)&p_w2t, g_w2t);

    cudaFuncSetAttribute(mma_gemm_kernel,
                         cudaFuncAttributeMaxDynamicSharedMemorySize, GEMM_SMEM);

    static cudaStream_t s_side = nullptr;
    static cudaEvent_t ev_root = nullptr, ev_csr = nullptr;
    if (!s_side) {
        cudaStreamCreateWithFlags(&s_side, cudaStreamNonBlocking);
        cudaEventCreateWithFlags(&ev_root, cudaEventDisableTiming);
        cudaEventCreateWithFlags(&ev_csr, cudaEventDisableTiming);
    }

    // main stream: converts
    conv_act_kernel<<<(NN * (KDIM / 4) + 255) / 256, 256>>>(x, p_xs, NN);
    conv_w_kernel<<<(KDIM * (HID1 + OUTC) + 255) / 256, 256>>>(W1, W2, p_w1t, p_w2t);

    // fork: CSR chain on side stream
    cudaEventRecord(ev_root, 0);
    cudaStreamWaitEvent(s_side, ev_root, 0);
    deg_kernel<<<(NTOT + 255) / 256, 256, 0, s_side>>>(ei);
    scan_kernel<<<1, 1024, 0, s_side>>>();
    scatter_kernel<<<(NTOT + 255) / 256, 256, 0, s_side>>>(ei);
    cudaEventRecord(ev_csr, s_side);

    // main stream: layer1 GEMM + fused alpha1 (overlaps CSR chain)
    mma_gemm_kernel<<<dim3(HID1 / BN, (NN + BM - 1) / BM), 256, GEMM_SMEM>>>(
        p_xs, p_w1t, p_h1, NN, HID1, KDIM, as1, ad1, p_as1, p_ad1, 8);

    // join: agg1 needs CSR + GEMM1
    cudaStreamWaitEvent(0, ev_csr, 0);
    agg1_kernel<<<NN, 256>>>(b1);

    // layer2 GEMM + fused alpha2
    mma_gemm_kernel<<<dim3(OUTC / BN, (NN + BM - 1) / BM), 256, GEMM_SMEM>>>(
        p_o1s, p_w2t, p_h2, NN, OUTC, KDIM, as2, ad2, p_as2, p_ad2, 1);

    // layer2 aggregation + log-softmax
    agg2_kernel<<<NN, 256>>>(b2, out);
}

// round 16
// speedup vs baseline: 1.7387x; 1.0542x over previous
#include <cuda_runtime.h>
#include <cuda_fp16.h>
#include <math.h>
#include <stdint.h>

#define NN     20000
#define INC    512
#define HID1   512      // H1*HID = 8*64
#define OUTC   256
#define NE     320000
#define NTOT   (NE + NN)   // edges + self loops = 340000
#define NEGS   0.2f
#define KDIM   512
#define CAP1   96
#define CAP2   128

// ---------------- scratch ----------------
__device__ __half g_h1[(size_t)NN * HID1];
__device__ __half g_h2[(size_t)NN * OUTC];
__device__ __half g_xs[(size_t)NN * KDIM];
__device__ __half g_o1s[(size_t)NN * KDIM];
__device__ __half g_w1t[(size_t)HID1 * KDIM];
__device__ __half g_w2t[(size_t)OUTC * KDIM];
__device__ float g_as1[NN * 8];
__device__ float g_ad1[NN * 8];
__device__ float g_as2[NN];
__device__ float g_ad2[NN];
__device__ int   g_deg[NN];      // zero at load; self-reset by scan each call
__device__ int   g_offs[NN + 1];
__device__ int   g_cursor[NN];
__device__ int   g_csr[NTOT];

// ---------------- helpers ----------------
__device__ __forceinline__ float warp_sum(float v) {
#pragma unroll
    for (int o = 16; o; o >>= 1) v += __shfl_xor_sync(0xffffffffu, v, o);
    return v;
}
__device__ __forceinline__ float warp_max(float v) {
#pragma unroll
    for (int o = 16; o; o >>= 1) v = fmaxf(v, __shfl_xor_sync(0xffffffffu, v, o));
    return v;
}
__device__ __forceinline__ unsigned fenc(float f) {
    unsigned u = __float_as_uint(f);
    return (u >> 31) ? ~u : (u | 0x80000000u);
}
__device__ __forceinline__ float fdec(unsigned u) {
    return __uint_as_float((u >> 31) ? (u & 0x7fffffffu) : ~u);
}
__device__ __forceinline__ float lrelu(float a) { return a > 0.f ? a : NEGS * a; }

__device__ __forceinline__ uint32_t smem_u32(const void* p) {
    return (uint32_t)__cvta_generic_to_shared(p);
}
__device__ __forceinline__ void ldsm_x4(uint32_t& r0, uint32_t& r1, uint32_t& r2, uint32_t& r3, uint32_t addr) {
    asm volatile("ldmatrix.sync.aligned.m8n8.x4.shared.b16 {%0,%1,%2,%3}, [%4];\n"
                 : "=r"(r0), "=r"(r1), "=r"(r2), "=r"(r3) : "r"(addr));
}
__device__ __forceinline__ void cp_async16(uint32_t dst, const void* src, bool pred) {
    int sz = pred ? 16 : 0;
    asm volatile("cp.async.cg.shared.global [%0], [%1], 16, %2;\n"
                 :: "r"(dst), "l"(src), "r"(sz));
}
__device__ __forceinline__ void cp_commit() {
    asm volatile("cp.async.commit_group;\n" ::: "memory");
}

// ---------------- CSR build ----------------
// histogram; also zeroes alpha2 accumulators (joins main stream before GEMM2)
__global__ void deg_kernel(const int* __restrict__ ei) {
    int i = blockIdx.x * blockDim.x + threadIdx.x;
    if (i < NN) { g_as2[i] = 0.f; g_ad2[i] = 0.f; }
    if (i < NTOT) {
        int d = (i < NE) ? ei[NE + i] : (i - NE);
        atomicAdd(&g_deg[d], 1);
    }
}
// scan; self-resets g_deg to zero for the next call
__global__ void scan_kernel() {
    __shared__ int warpsum[32];
    __shared__ int carry;
    int tid = threadIdx.x, lane = tid & 31, w = tid >> 5;
    if (tid == 0) { carry = 0; g_offs[0] = 0; }
    __syncthreads();
    for (int base = 0; base < NN; base += 1024) {
        int i = base + tid;
        int v = (i < NN) ? g_deg[i] : 0;
        if (i < NN) g_deg[i] = 0;
        int x = v;
#pragma unroll
        for (int o = 1; o < 32; o <<= 1) {
            int t = __shfl_up_sync(0xffffffffu, x, o);
            if (lane >= o) x += t;
        }
        if (lane == 31) warpsum[w] = x;
        __syncthreads();
        if (w == 0) {
            int s = warpsum[lane];
#pragma unroll
            for (int o = 1; o < 32; o <<= 1) {
                int t = __shfl_up_sync(0xffffffffu, s, o);
                if (lane >= o) s += t;
            }
            warpsum[lane] = s;
        }
        __syncthreads();
        int incl = carry + (w ? warpsum[w - 1] : 0) + x;
        if (i < NN) {
            g_offs[i + 1] = incl;
            g_cursor[i] = incl - v;
        }
        __syncthreads();
        if (tid == 1023) carry = incl;
        __syncthreads();
    }
}
__global__ void scatter_kernel(const int* __restrict__ ei) {
    int i = blockIdx.x * blockDim.x + threadIdx.x;
    if (i < NTOT) {
        int s, d;
        if (i < NE) { s = ei[i]; d = ei[NE + i]; }
        else        { s = d = i - NE; }
        int p = atomicAdd(&g_cursor[d], 1);
        g_csr[p] = s;
    }
}

// ---------------- fp16 conversions ----------------
// act convert + W1 convert in one kernel (both needed only by GEMM1)
__global__ void conv_actw1_kernel(const float* __restrict__ in, __half* __restrict__ out,
                                  const float* __restrict__ W1, __half* __restrict__ w1t) {
    int idx = blockIdx.x * blockDim.x + threadIdx.x;
    if (idx < KDIM * HID1) {
        int n = idx / KDIM, k = idx % KDIM;
        w1t[(size_t)n * KDIM + k] = __float2half(W1[(size_t)k * HID1 + n]);
    }
    int total = NN * (KDIM / 4);
    if (idx >= total) return;
    int c4 = idx * 4;
    float4 v = *(const float4*)(in + c4);
    __half h0 = __float2half(v.x), h1 = __float2half(v.y);
    __half h2 = __float2half(v.z), h3 = __float2half(v.w);
    *(ushort4*)(out + c4) = make_ushort4(
        *(unsigned short*)&h0, *(unsigned short*)&h1,
        *(unsigned short*)&h2, *(unsigned short*)&h3);
}
// W2 convert (only needed by GEMM2; runs hidden on the side stream)
__global__ void conv_w2_kernel(const float* __restrict__ W2, __half* __restrict__ w2t) {
    int idx = blockIdx.x * blockDim.x + threadIdx.x;
    if (idx >= KDIM * OUTC) return;
    int n = idx / KDIM, k = idx % KDIM;
    w2t[(size_t)n * KDIM + k] = __float2half(W2[(size_t)k * OUTC + n]);
}

// ---------------- fp16 tensor-core GEMM (NT), BK=64, 3-stage cp.async ----------------
#define BM 128
#define BN 128
#define BK 64
#define APAD 72
#define NSTAGE 3
#define GEMM_SMEM (NSTAGE * (BM + BN) * APAD * 2)   // 110592 bytes

__global__ __launch_bounds__(256, 2) void mma_gemm_kernel(
    const __half* __restrict__ A, const __half* __restrict__ Bt,
    __half* __restrict__ C, int M, int Nc, int K,
    const float* __restrict__ asrc, const float* __restrict__ adst,
    float* __restrict__ oas, float* __restrict__ oad, int heads)
{
    extern __shared__ __half sm[];
    const int STG = (BM + BN) * APAD;

    int tid = threadIdx.x;
    int warp = tid >> 5, lane = tid & 31;
    int wm = (warp & 3) * 32;
    int wn = (warp >> 2) * 64;
    int m0 = blockIdx.y * BM, n0 = blockIdx.x * BN;
    int g = lane >> 2, t4 = lane & 3;

    int a_row = (lane & 7) + ((lane >> 3) & 1) * 8;
    int a_half = (lane >> 4) * 8;
    int b_row = (lane & 7) + ((lane >> 4) << 3);
    int b_half = ((lane >> 3) & 1) * 8;

    int r0 = tid >> 3;
    int cq = (tid & 7) * 8;
    bool am[4];
#pragma unroll
    for (int i = 0; i < 4; i++) am[i] = (m0 + r0 + 32 * i) < M;
    const __half* gA = A + (size_t)(m0 + r0) * K + cq;
    const __half* gB = Bt + (size_t)(n0 + r0) * K + cq;

    float acc[2][8][4];
#pragma unroll
    for (int mi = 0; mi < 2; mi++)
#pragma unroll
        for (int ni = 0; ni < 8; ni++)
#pragma unroll
            for (int j = 0; j < 4; j++) acc[mi][ni][j] = 0.f;

    int nk = K / BK;   // 8

#define ISSUE(KT) {                                                               \
        int _buf = (KT) % NSTAGE;                                                 \
        int _k0 = (KT) * BK;                                                      \
        __half* sA = sm + _buf * STG;                                             \
        __half* sB = sA + BM * APAD;                                              \
        _Pragma("unroll")                                                         \
        for (int i = 0; i < 4; i++) {                                             \
            int rr = r0 + 32 * i;                                                 \
            cp_async16(smem_u32(sA + rr * APAD + cq), gA + (size_t)32 * i * K + _k0, am[i]); \
            cp_async16(smem_u32(sB + rr * APAD + cq), gB + (size_t)32 * i * K + _k0, true);  \
        }                                                                         \
        cp_commit();                                                              \
    }

    ISSUE(0);
    ISSUE(1);

    for (int kt = 0; kt < nk; kt++) {
        asm volatile("cp.async.wait_group 1;\n" ::: "memory");
        __syncthreads();
        if (kt + 2 < nk) { ISSUE(kt + 2); }
        else             { cp_commit(); }

        __half* sA = sm + (kt % NSTAGE) * STG;
        __half* sB = sA + BM * APAD;
#pragma unroll
        for (int kk = 0; kk < 4; kk++) {
            int kb = kk * 16;
            uint32_t af[2][4];
            uint32_t bfrag[8][2];
#pragma unroll
            for (int mi = 0; mi < 2; mi++) {
                uint32_t ad = smem_u32(sA + (wm + mi * 16 + a_row) * APAD + kb + a_half);
                ldsm_x4(af[mi][0], af[mi][1], af[mi][2], af[mi][3], ad);
            }
#pragma unroll
            for (int p = 0; p < 4; p++) {
                uint32_t bd = smem_u32(sB + (wn + p * 16 + b_row) * APAD + kb + b_half);
                ldsm_x4(bfrag[2 * p][0], bfrag[2 * p][1], bfrag[2 * p + 1][0], bfrag[2 * p + 1][1], bd);
            }
#pragma unroll
            for (int mi = 0; mi < 2; mi++)
#pragma unroll
                for (int ni = 0; ni < 8; ni++) {
                    asm volatile(
                        "mma.sync.aligned.m16n8k16.row.col.f32.f16.f16.f32 "
                        "{%0,%1,%2,%3}, {%4,%5,%6,%7}, {%8,%9}, {%0,%1,%2,%3};\n"
                        : "+f"(acc[mi][ni][0]), "+f"(acc[mi][ni][1]),
                          "+f"(acc[mi][ni][2]), "+f"(acc[mi][ni][3])
                        : "r"(af[mi][0]), "r"(af[mi][1]), "r"(af[mi][2]), "r"(af[mi][3]),
                          "r"(bfrag[ni][0]), "r"(bfrag[ni][1]));
                }
        }
    }
#undef ISSUE

#pragma unroll
    for (int mi = 0; mi < 2; mi++) {
        int r = m0 + wm + mi * 16;
#pragma unroll
        for (int ni = 0; ni < 8; ni++) {
            int c = n0 + wn + ni * 8 + 2 * t4;
            if (r + g < M) {
                __half2 v0 = __floats2half2_rn(acc[mi][ni][0], acc[mi][ni][1]);
                *(__half2*)(C + (size_t)(r + g) * Nc + c) = v0;
            }
            if (r + g + 8 < M) {
                __half2 v1 = __floats2half2_rn(acc[mi][ni][2], acc[mi][ni][3]);
                *(__half2*)(C + (size_t)(r + g + 8) * Nc + c) = v1;
            }
        }
    }

    if (asrc) {
#pragma unroll
        for (int mi = 0; mi < 2; mi++) {
            float s0 = 0.f, s1 = 0.f, d0 = 0.f, d1 = 0.f;
#pragma unroll
            for (int ni = 0; ni < 8; ni++) {
#pragma unroll
                for (int j = 0; j < 2; j++) {
                    int c = n0 + wn + ni * 8 + 2 * t4 + j;
                    float a_s = asrc[c], a_d = adst[c];
                    s0 += acc[mi][ni][j] * a_s;
                    d0 += acc[mi][ni][j] * a_d;
                    s1 += acc[mi][ni][j + 2] * a_s;
                    d1 += acc[mi][ni][j + 2] * a_d;
                }
            }
#pragma unroll
            for (int o = 1; o < 4; o <<= 1) {
                s0 += __shfl_xor_sync(0xffffffffu, s0, o);
                s1 += __shfl_xor_sync(0xffffffffu, s1, o);
                d0 += __shfl_xor_sync(0xffffffffu, d0, o);
                d1 += __shfl_xor_sync(0xffffffffu, d1, o);
            }
            if (t4 == 0) {
                int r0w = m0 + wm + mi * 16 + g;
                int r1w = r0w + 8;
                if (heads == 8) {
                    int head = (n0 + wn) >> 6;
                    if (r0w < M) { oas[r0w * 8 + head] = s0; oad[r0w * 8 + head] = d0; }
                    if (r1w < M) { oas[r1w * 8 + head] = s1; oad[r1w * 8 + head] = d1; }
                } else {
                    if (r0w < M) { atomicAdd(&oas[r0w], s0); atomicAdd(&oad[r0w], d0); }
                    if (r1w < M) { atomicAdd(&oas[r1w], s1); atomicAdd(&oad[r1w], d1); }
                }
            }
        }
    }
}

// ---------------- layer1 aggregation: deferred-normalization softmax + fp16 gather ----------------
__global__ void agg1_kernel(const float* __restrict__ bias) {
    int n = blockIdx.x;
    int tid = threadIdx.x;
    int beg = g_offs[n], end = g_offs[n + 1];
    int deg = end - beg;

    __shared__ float s_ad[8];
    __shared__ float s_max[8];
    __shared__ float s_inv[8];
    __shared__ int   s_src[CAP1];
    __shared__ float s_alpha[CAP1][9];
    __shared__ unsigned s_maxi[8];
    __shared__ float s_sum8[8];

    if (tid < 8) {
        s_ad[tid] = g_ad1[n * 8 + tid];
        s_maxi[tid] = 0x007FFFFFu;
        s_sum8[tid] = 0.f;
    }
    __syncthreads();

    int c = 2 * tid;
    int hch = c >> 6;
    float accx = 0.f, accy = 0.f;

    if (deg <= CAP1) {
        for (int base = 0; base < deg; base += 32) {
            int el = base + (tid >> 3), hh = tid & 7;
            if (el < deg) {
                int s = g_csr[beg + el];
                if (hh == 0) s_src[el] = s;
                s_alpha[el][hh] = lrelu(g_as1[s * 8 + hh] + s_ad[hh]);
            }
        }
        __syncthreads();
        // per-head softmax (warp h): store raw exp; normalization deferred to accumulator
        {
            int h = tid >> 5, l = tid & 31;
            float m = -INFINITY;
            for (int e = l; e < deg; e += 32) m = fmaxf(m, s_alpha[e][h]);
            m = warp_max(m);
            float ssum = 0.f;
            for (int e = l; e < deg; e += 32) {
                float ex = __expf(s_alpha[e][h] - m);
                s_alpha[e][h] = ex;
                ssum += ex;
            }
            ssum = warp_sum(ssum);
            if (l == 0) s_inv[h] = 1.f / (ssum + 1e-16f);
        }
        __syncthreads();
        int e = 0;
        for (; e + 8 <= deg; e += 8) {
            float2 v0 = __half22float2(*(const __half2*)(g_h1 + (size_t)s_src[e + 0] * HID1 + c));
            float2 v1 = __half22float2(*(const __half2*)(g_h1 + (size_t)s_src[e + 1] * HID1 + c));
            float2 v2 = __half22float2(*(const __half2*)(g_h1 + (size_t)s_src[e + 2] * HID1 + c));
            float2 v3 = __half22float2(*(const __half2*)(g_h1 + (size_t)s_src[e + 3] * HID1 + c));
            float2 v4 = __half22float2(*(const __half2*)(g_h1 + (size_t)s_src[e + 4] * HID1 + c));
            float2 v5 = __half22float2(*(const __half2*)(g_h1 + (size_t)s_src[e + 5] * HID1 + c));
            float2 v6 = __half22float2(*(const __half2*)(g_h1 + (size_t)s_src[e + 6] * HID1 + c));
            float2 v7 = __half22float2(*(const __half2*)(g_h1 + (size_t)s_src[e + 7] * HID1 + c));
            float k0 = s_alpha[e + 0][hch], k1 = s_alpha[e + 1][hch];
            float k2 = s_alpha[e + 2][hch], k3 = s_alpha[e + 3][hch];
            float k4 = s_alpha[e + 4][hch], k5 = s_alpha[e + 5][hch];
            float k6 = s_alpha[e + 6][hch], k7 = s_alpha[e + 7][hch];
            accx += v0.x * k0 + v1.x * k1 + v2.x * k2 + v3.x * k3
                  + v4.x * k4 + v5.x * k5 + v6.x * k6 + v7.x * k7;
            accy += v0.y * k0 + v1.y * k1 + v2.y * k2 + v3.y * k3
                  + v4.y * k4 + v5.y * k5 + v6.y * k6 + v7.y * k7;
        }
        for (; e + 4 <= deg; e += 4) {
            float2 v0 = __half22float2(*(const __half2*)(g_h1 + (size_t)s_src[e + 0] * HID1 + c));
            float2 v1 = __half22float2(*(const __half2*)(g_h1 + (size_t)s_src[e + 1] * HID1 + c));
            float2 v2 = __half22float2(*(const __half2*)(g_h1 + (size_t)s_src[e + 2] * HID1 + c));
            float2 v3 = __half22float2(*(const __half2*)(g_h1 + (size_t)s_src[e + 3] * HID1 + c));
            float k0 = s_alpha[e + 0][hch], k1 = s_alpha[e + 1][hch];
            float k2 = s_alpha[e + 2][hch], k3 = s_alpha[e + 3][hch];
            accx += v0.x * k0 + v1.x * k1 + v2.x * k2 + v3.x * k3;
            accy += v0.y * k0 + v1.y * k1 + v2.y * k2 + v3.y * k3;
        }
        for (; e < deg; e++) {
            float2 v = __half22float2(*(const __half2*)(g_h1 + (size_t)s_src[e] * HID1 + c));
            float kc = s_alpha[e][hch];
            accx += v.x * kc;
            accy += v.y * kc;
        }
        float inv = s_inv[hch];
        accx *= inv;
        accy *= inv;
    } else {
        const float4* as4 = (const float4*)g_as1;
        float lmax[8];
#pragma unroll
        for (int h = 0; h < 8; h++) lmax[h] = -INFINITY;
        for (int e = beg + tid; e < end; e += 256) {
            int s = g_csr[e];
            float4 lo = as4[s * 2], hi = as4[s * 2 + 1];
            float av[8] = {lo.x, lo.y, lo.z, lo.w, hi.x, hi.y, hi.z, hi.w};
#pragma unroll
            for (int h = 0; h < 8; h++) lmax[h] = fmaxf(lmax[h], lrelu(av[h] + s_ad[h]));
        }
#pragma unroll
        for (int h = 0; h < 8; h++) atomicMax(&s_maxi[h], fenc(lmax[h]));
        __syncthreads();
        if (tid < 8) s_max[tid] = fdec(s_maxi[tid]);
        __syncthreads();
        float lsum[8];
#pragma unroll
        for (int h = 0; h < 8; h++) lsum[h] = 0.f;
        for (int e = beg + tid; e < end; e += 256) {
            int s = g_csr[e];
            float4 lo = as4[s * 2], hi = as4[s * 2 + 1];
            float av[8] = {lo.x, lo.y, lo.z, lo.w, hi.x, hi.y, hi.z, hi.w};
#pragma unroll
            for (int h = 0; h < 8; h++) lsum[h] += __expf(lrelu(av[h] + s_ad[h]) - s_max[h]);
        }
#pragma unroll
        for (int h = 0; h < 8; h++) atomicAdd(&s_sum8[h], lsum[h]);
        __syncthreads();
        if (tid < 8) s_inv[tid] = 1.f / (s_sum8[tid] + 1e-16f);
        __syncthreads();
        for (int cb = beg; cb < end; cb += 32) {
            int cn = end - cb; if (cn > 32) cn = 32;
            int el = tid >> 3, hh = tid & 7;
            if (el < cn) {
                int s = g_csr[cb + el];
                float a = lrelu(g_as1[s * 8 + hh] + s_ad[hh]);
                s_alpha[el][hh] = __expf(a - s_max[hh]) * s_inv[hh];
                if (hh == 0) s_src[el] = s;
            }
            __syncthreads();
            for (int e = 0; e < cn; e++) {
                float2 v = __half22float2(*(const __half2*)(g_h1 + (size_t)s_src[e] * HID1 + c));
                float kc = s_alpha[e][hch];
                accx += v.x * kc;
                accy += v.y * kc;
            }
            __syncthreads();
        }
    }

    float2 bv = *(const float2*)(bias + c);
    float ox = accx + bv.x, oy = accy + bv.y;
    ox = ox > 0.f ? ox : expm1f(ox);
    oy = oy > 0.f ? oy : expm1f(oy);
    __half hx = __float2half(ox), hy = __float2half(oy);
    *(ushort2*)(g_o1s + (size_t)n * KDIM + c) =
        make_ushort2(*(unsigned short*)&hx, *(unsigned short*)&hy);
}

// ---------------- layer2 aggregation: deferred-normalization softmax + log-softmax ----------------
__global__ void agg2_kernel(const float* __restrict__ bias, float* __restrict__ out) {
    int n = blockIdx.x;
    int tid = threadIdx.x;
    int beg = g_offs[n], end = g_offs[n + 1];
    int deg = end - beg;

    __shared__ float s_ad;
    __shared__ float s_max;
    __shared__ float s_inv;
    __shared__ unsigned s_maxi;
    __shared__ float s_sum1;
    __shared__ int   s_src[CAP2];
    __shared__ float s_alpha[CAP2];
    __shared__ float shm[8];
    __shared__ float shs[8];

    if (tid == 0) {
        s_ad = g_ad2[n];
        s_maxi = 0x007FFFFFu;
        s_sum1 = 0.f;
    }
    __syncthreads();

    float acc = 0.f;
    bool fast = (deg <= CAP2);

    if (fast) {
        if (tid < deg) {
            int s = g_csr[beg + tid];
            s_src[tid] = s;
            s_alpha[tid] = lrelu(g_as2[s] + s_ad);
        }
        __syncthreads();
        if (tid < 32) {
            float m = -INFINITY;
            for (int e = tid; e < deg; e += 32) m = fmaxf(m, s_alpha[e]);
            m = warp_max(m);
            float ssum = 0.f;
            for (int e = tid; e < deg; e += 32) {
                float ex = __expf(s_alpha[e] - m);
                s_alpha[e] = ex;
                ssum += ex;
            }
            ssum = warp_sum(ssum);
            if (tid == 0) s_inv = 1.f / (ssum + 1e-16f);
        }
        __syncthreads();
        int e = 0;
        for (; e + 8 <= deg; e += 8) {
            float v0 = __half2float(g_h2[(size_t)s_src[e + 0] * OUTC + tid]);
            float v1 = __half2float(g_h2[(size_t)s_src[e + 1] * OUTC + tid]);
            float v2 = __half2float(g_h2[(size_t)s_src[e + 2] * OUTC + tid]);
            float v3 = __half2float(g_h2[(size_t)s_src[e + 3] * OUTC + tid]);
            float v4 = __half2float(g_h2[(size_t)s_src[e + 4] * OUTC + tid]);
            float v5 = __half2float(g_h2[(size_t)s_src[e + 5] * OUTC + tid]);
            float v6 = __half2float(g_h2[(size_t)s_src[e + 6] * OUTC + tid]);
            float v7 = __half2float(g_h2[(size_t)s_src[e + 7] * OUTC + tid]);
            acc += v0 * s_alpha[e + 0] + v1 * s_alpha[e + 1] + v2 * s_alpha[e + 2] + v3 * s_alpha[e + 3]
                 + v4 * s_alpha[e + 4] + v5 * s_alpha[e + 5] + v6 * s_alpha[e + 6] + v7 * s_alpha[e + 7];
        }
        for (; e + 4 <= deg; e += 4) {
            float v0 = __half2float(g_h2[(size_t)s_src[e + 0] * OUTC + tid]);
            float v1 = __half2float(g_h2[(size_t)s_src[e + 1] * OUTC + tid]);
            float v2 = __half2float(g_h2[(size_t)s_src[e + 2] * OUTC + tid]);
            float v3 = __half2float(g_h2[(size_t)s_src[e + 3] * OUTC + tid]);
            acc += v0 * s_alpha[e + 0] + v1 * s_alpha[e + 1] + v2 * s_alpha[e + 2] + v3 * s_alpha[e + 3];
        }
        for (; e < deg; e++) acc += __half2float(g_h2[(size_t)s_src[e] * OUTC + tid]) * s_alpha[e];
        acc *= s_inv;
    } else {
        float lmax = -INFINITY;
        for (int e = beg + tid; e < end; e += 256) {
            float a = lrelu(g_as2[g_csr[e]] + s_ad);
            lmax = fmaxf(lmax, a);
        }
        atomicMax(&s_maxi, fenc(lmax));
        __syncthreads();
        if (tid == 0) s_max = fdec(s_maxi);
        __syncthreads();
        float lsum = 0.f;
        for (int e = beg + tid; e < end; e += 256) {
            float a = lrelu(g_as2[g_csr[e]] + s_ad);
            lsum += __expf(a - s_max);
        }
        atomicAdd(&s_sum1, lsum);
        __syncthreads();
        if (tid == 0) s_inv = 1.f / (s_sum1 + 1e-16f);
        __syncthreads();
        for (int cb = beg; cb < end; cb += CAP2) {
            int cn = end - cb; if (cn > CAP2) cn = CAP2;
            if (tid < cn) {
                int s = g_csr[cb + tid];
                float a = lrelu(g_as2[s] + s_ad);
                s_alpha[tid] = __expf(a - s_max) * s_inv;
                s_src[tid] = s;
            }
            __syncthreads();
            for (int e = 0; e < cn; e++)
                acc += __half2float(g_h2[(size_t)s_src[e] * OUTC + tid]) * s_alpha[e];
            __syncthreads();
        }
    }

    float v = acc + bias[tid];
    float wm = warp_max(v);
    if ((tid & 31) == 0) shm[tid >> 5] = wm;
    __syncthreads();
    float m = shm[0];
#pragma unroll
    for (int i = 1; i < 8; i++) m = fmaxf(m, shm[i]);
    float ex = __expf(v - m);
    float ws = warp_sum(ex);
    if ((tid & 31) == 0) shs[tid >> 5] = ws;
    __syncthreads();
    float s = 0.f;
#pragma unroll
    for (int i = 0; i < 8; i++) s += shs[i];
    out[(size_t)n * OUTC + tid] = v - m - __logf(s);
}

// ---------------- launch (fork at t=0: CSR chain fully hidden under conv+GEMM1) ----------------
extern "C" void kernel_launch(void* const* d_in, const int* in_sizes, int n_in,
                              void* d_out, int out_size) {
    const float* x    = (const float*)d_in[0];
    const int*   ei   = (const int*)d_in[1];
    const float* W1   = (const float*)d_in[2];
    const float* as1  = (const float*)d_in[3];
    const float* ad1  = (const float*)d_in[4];
    const float* b1   = (const float*)d_in[5];
    const float* W2   = (const float*)d_in[6];
    const float* as2  = (const float*)d_in[7];
    const float* ad2  = (const float*)d_in[8];
    const float* b2   = (const float*)d_in[9];
    float* out = (float*)d_out;

    float *p_as1, *p_ad1, *p_as2, *p_ad2;
    __half *p_h1, *p_h2, *p_xs, *p_o1s, *p_w1t, *p_w2t;
    cudaGetSymbolAddress((void**)&p_h1, g_h1);
    cudaGetSymbolAddress((void**)&p_h2, g_h2);
    cudaGetSymbolAddress((void**)&p_as1, g_as1);
    cudaGetSymbolAddress((void**)&p_ad1, g_ad1);
    cudaGetSymbolAddress((void**)&p_as2, g_as2);
    cudaGetSymbolAddress((void**)&p_ad2, g_ad2);
    cudaGetSymbolAddress((void**)&p_xs, g_xs);
    cudaGetSymbolAddress((void**)&p_o1s, g_o1s);
    cudaGetSymbolAddress((void**)&p_w1t, g_w1t);
    cudaGetSymbolAddress((void**)&p_w2t, g_w2t);

    cudaFuncSetAttribute(mma_gemm_kernel,
                         cudaFuncAttributeMaxDynamicSharedMemorySize, GEMM_SMEM);

    static cudaStream_t s_side = nullptr;
    static cudaEvent_t ev_root = nullptr, ev_csr = nullptr;
    if (!s_side) {
        cudaStreamCreateWithFlags(&s_side, cudaStreamNonBlocking);
        cudaEventCreateWithFlags(&ev_root, cudaEventDisableTiming);
        cudaEventCreateWithFlags(&ev_csr, cudaEventDisableTiming);
    }

    // fork FIRST: side chain starts at graph t=0
    cudaEventRecord(ev_root, 0);
    cudaStreamWaitEvent(s_side, ev_root, 0);
    deg_kernel<<<(NTOT + 255) / 256, 256, 0, s_side>>>(ei);
    scan_kernel<<<1, 1024, 0, s_side>>>();
    scatter_kernel<<<(NTOT + 255) / 256, 256, 0, s_side>>>(ei);
    conv_w2_kernel<<<(KDIM * OUTC + 255) / 256, 256, 0, s_side>>>(W2, p_w2t);
    cudaEventRecord(ev_csr, s_side);

    // main stream: act+W1 convert, then GEMM1 (overlaps CSR chain)
    conv_actw1_kernel<<<(NN * (KDIM / 4) + 255) / 256, 256>>>(x, p_xs, W1, p_w1t);
    mma_gemm_kernel<<<dim3(HID1 / BN, (NN + BM - 1) / BM), 256, GEMM_SMEM>>>(
        p_xs, p_w1t, p_h1, NN, HID1, KDIM, as1, ad1, p_as1, p_ad1, 8);

    // join: agg1 needs CSR + GEMM1 (w2t also ready by here)
    cudaStreamWaitEvent(0, ev_csr, 0);
    agg1_kernel<<<NN, 256>>>(b1);

    // layer2 GEMM + fused alpha2
    mma_gemm_kernel<<<dim3(OUTC / BN, (NN + BM - 1) / BM), 256, GEMM_SMEM>>>(
        p_o1s, p_w2t, p_h2, NN, OUTC, KDIM, as2, ad2, p_as2, p_ad2, 1);

    // layer2 aggregation + log-softmax
    agg2_kernel<<<NN, 256>>>(b2, out);
}

// round 17
// speedup vs baseline: 1.8850x; 1.0841x over previous
#include <cuda_runtime.h>
#include <cuda_fp16.h>
#include <math.h>
#include <stdint.h>

#define NN     20000
#define INC    512
#define HID1   512      // H1*HID = 8*64
#define OUTC   256
#define NE     320000
#define NTOT   (NE + NN)   // edges + self loops = 340000
#define NEGS   0.2f
#define KDIM   512
#define CAP1   96
#define CAP2   128
#define SPLIT  10112     // 79 * 128: agg1 / GEMM2 pipeline split point

// ---------------- scratch ----------------
__device__ __half g_h1[(size_t)NN * HID1];
__device__ __half g_h2[(size_t)NN * OUTC];
__device__ __half g_xs[(size_t)NN * KDIM];
__device__ __half g_o1s[(size_t)NN * KDIM];
__device__ __half g_w1t[(size_t)HID1 * KDIM];
__device__ __half g_w2t[(size_t)OUTC * KDIM];
__device__ float g_as1[NN * 8];
__device__ float g_ad1[NN * 8];
__device__ float g_as2[NN];
__device__ float g_ad2[NN];
__device__ int   g_deg[NN];      // zero at load; self-reset by scan each call
__device__ int   g_offs[NN + 1];
__device__ int   g_cursor[NN];
__device__ int   g_csr[NTOT];

// ---------------- helpers ----------------
__device__ __forceinline__ float warp_sum(float v) {
#pragma unroll
    for (int o = 16; o; o >>= 1) v += __shfl_xor_sync(0xffffffffu, v, o);
    return v;
}
__device__ __forceinline__ float warp_max(float v) {
#pragma unroll
    for (int o = 16; o; o >>= 1) v = fmaxf(v, __shfl_xor_sync(0xffffffffu, v, o));
    return v;
}
__device__ __forceinline__ unsigned fenc(float f) {
    unsigned u = __float_as_uint(f);
    return (u >> 31) ? ~u : (u | 0x80000000u);
}
__device__ __forceinline__ float fdec(unsigned u) {
    return __uint_as_float((u >> 31) ? (u & 0x7fffffffu) : ~u);
}
__device__ __forceinline__ float lrelu(float a) { return a > 0.f ? a : NEGS * a; }

__device__ __forceinline__ uint32_t smem_u32(const void* p) {
    return (uint32_t)__cvta_generic_to_shared(p);
}
__device__ __forceinline__ void ldsm_x4(uint32_t& r0, uint32_t& r1, uint32_t& r2, uint32_t& r3, uint32_t addr) {
    asm volatile("ldmatrix.sync.aligned.m8n8.x4.shared.b16 {%0,%1,%2,%3}, [%4];\n"
                 : "=r"(r0), "=r"(r1), "=r"(r2), "=r"(r3) : "r"(addr));
}
__device__ __forceinline__ void cp_async16(uint32_t dst, const void* src, bool pred) {
    int sz = pred ? 16 : 0;
    asm volatile("cp.async.cg.shared.global [%0], [%1], 16, %2;\n"
                 :: "r"(dst), "l"(src), "r"(sz));
}
__device__ __forceinline__ void cp_commit() {
    asm volatile("cp.async.commit_group;\n" ::: "memory");
}

// ---------------- CSR build ----------------
__global__ void deg_kernel(const int* __restrict__ ei) {
    int i = blockIdx.x * blockDim.x + threadIdx.x;
    if (i < NN) { g_as2[i] = 0.f; g_ad2[i] = 0.f; }
    if (i < NTOT) {
        int d = (i < NE) ? ei[NE + i] : (i - NE);
        atomicAdd(&g_deg[d], 1);
    }
}
__global__ void scan_kernel() {
    __shared__ int warpsum[32];
    __shared__ int carry;
    int tid = threadIdx.x, lane = tid & 31, w = tid >> 5;
    if (tid == 0) { carry = 0; g_offs[0] = 0; }
    __syncthreads();
    for (int base = 0; base < NN; base += 1024) {
        int i = base + tid;
        int v = (i < NN) ? g_deg[i] : 0;
        if (i < NN) g_deg[i] = 0;
        int x = v;
#pragma unroll
        for (int o = 1; o < 32; o <<= 1) {
            int t = __shfl_up_sync(0xffffffffu, x, o);
            if (lane >= o) x += t;
        }
        if (lane == 31) warpsum[w] = x;
        __syncthreads();
        if (w == 0) {
            int s = warpsum[lane];
#pragma unroll
            for (int o = 1; o < 32; o <<= 1) {
                int t = __shfl_up_sync(0xffffffffu, s, o);
                if (lane >= o) s += t;
            }
            warpsum[lane] = s;
        }
        __syncthreads();
        int incl = carry + (w ? warpsum[w - 1] : 0) + x;
        if (i < NN) {
            g_offs[i + 1] = incl;
            g_cursor[i] = incl - v;
        }
        __syncthreads();
        if (tid == 1023) carry = incl;
        __syncthreads();
    }
}
__global__ void scatter_kernel(const int* __restrict__ ei) {
    int i = blockIdx.x * blockDim.x + threadIdx.x;
    if (i < NTOT) {
        int s, d;
        if (i < NE) { s = ei[i]; d = ei[NE + i]; }
        else        { s = d = i - NE; }
        int p = atomicAdd(&g_cursor[d], 1);
        g_csr[p] = s;
    }
}

// ---------------- fp16 conversions ----------------
__global__ void conv_actw1_kernel(const float* __restrict__ in, __half* __restrict__ out,
                                  const float* __restrict__ W1, __half* __restrict__ w1t) {
    int idx = blockIdx.x * blockDim.x + threadIdx.x;
    if (idx < KDIM * HID1) {
        int n = idx / KDIM, k = idx % KDIM;
        w1t[(size_t)n * KDIM + k] = __float2half(W1[(size_t)k * HID1 + n]);
    }
    int total = NN * (KDIM / 4);
    if (idx >= total) return;
    int c4 = idx * 4;
    float4 v = *(const float4*)(in + c4);
    __half h0 = __float2half(v.x), h1 = __float2half(v.y);
    __half h2 = __float2half(v.z), h3 = __float2half(v.w);
    *(ushort4*)(out + c4) = make_ushort4(
        *(unsigned short*)&h0, *(unsigned short*)&h1,
        *(unsigned short*)&h2, *(unsigned short*)&h3);
}
__global__ void conv_w2_kernel(const float* __restrict__ W2, __half* __restrict__ w2t) {
    int idx = blockIdx.x * blockDim.x + threadIdx.x;
    if (idx >= KDIM * OUTC) return;
    int n = idx / KDIM, k = idx % KDIM;
    w2t[(size_t)n * KDIM + k] = __float2half(W2[(size_t)k * OUTC + n]);
}

// ---------------- fp16 tensor-core GEMM (NT), BK=64, 3-stage cp.async ----------------
#define BM 128
#define BN 128
#define BK 64
#define APAD 72
#define NSTAGE 3
#define GEMM_SMEM (NSTAGE * (BM + BN) * APAD * 2)   // 110592 bytes

__global__ __launch_bounds__(256, 2) void mma_gemm_kernel(
    const __half* __restrict__ A, const __half* __restrict__ Bt,
    __half* __restrict__ C, int M, int Nc, int K,
    const float* __restrict__ asrc, const float* __restrict__ adst,
    float* __restrict__ oas, float* __restrict__ oad, int heads)
{
    extern __shared__ __half sm[];
    const int STG = (BM + BN) * APAD;

    int tid = threadIdx.x;
    int warp = tid >> 5, lane = tid & 31;
    int wm = (warp & 3) * 32;
    int wn = (warp >> 2) * 64;
    int m0 = blockIdx.y * BM, n0 = blockIdx.x * BN;
    int g = lane >> 2, t4 = lane & 3;

    int a_row = (lane & 7) + ((lane >> 3) & 1) * 8;
    int a_half = (lane >> 4) * 8;
    int b_row = (lane & 7) + ((lane >> 4) << 3);
    int b_half = ((lane >> 3) & 1) * 8;

    int r0 = tid >> 3;
    int cq = (tid & 7) * 8;
    bool am[4];
#pragma unroll
    for (int i = 0; i < 4; i++) am[i] = (m0 + r0 + 32 * i) < M;
    const __half* gA = A + (size_t)(m0 + r0) * K + cq;
    const __half* gB = Bt + (size_t)(n0 + r0) * K + cq;

    float acc[2][8][4];
#pragma unroll
    for (int mi = 0; mi < 2; mi++)
#pragma unroll
        for (int ni = 0; ni < 8; ni++)
#pragma unroll
            for (int j = 0; j < 4; j++) acc[mi][ni][j] = 0.f;

    int nk = K / BK;   // 8

#define ISSUE(KT) {                                                               \
        int _buf = (KT) % NSTAGE;                                                 \
        int _k0 = (KT) * BK;                                                      \
        __half* sA = sm + _buf * STG;                                             \
        __half* sB = sA + BM * APAD;                                              \
        _Pragma("unroll")                                                         \
        for (int i = 0; i < 4; i++) {                                             \
            int rr = r0 + 32 * i;                                                 \
            cp_async16(smem_u32(sA + rr * APAD + cq), gA + (size_t)32 * i * K + _k0, am[i]); \
            cp_async16(smem_u32(sB + rr * APAD + cq), gB + (size_t)32 * i * K + _k0, true);  \
        }                                                                         \
        cp_commit();                                                              \
    }

    ISSUE(0);
    ISSUE(1);

    for (int kt = 0; kt < nk; kt++) {
        asm volatile("cp.async.wait_group 1;\n" ::: "memory");
        __syncthreads();
        if (kt + 2 < nk) { ISSUE(kt + 2); }
        else             { cp_commit(); }

        __half* sA = sm + (kt % NSTAGE) * STG;
        __half* sB = sA + BM * APAD;
#pragma unroll
        for (int kk = 0; kk < 4; kk++) {
            int kb = kk * 16;
            uint32_t af[2][4];
            uint32_t bfrag[8][2];
#pragma unroll
            for (int mi = 0; mi < 2; mi++) {
                uint32_t ad = smem_u32(sA + (wm + mi * 16 + a_row) * APAD + kb + a_half);
                ldsm_x4(af[mi][0], af[mi][1], af[mi][2], af[mi][3], ad);
            }
#pragma unroll
            for (int p = 0; p < 4; p++) {
                uint32_t bd = smem_u32(sB + (wn + p * 16 + b_row) * APAD + kb + b_half);
                ldsm_x4(bfrag[2 * p][0], bfrag[2 * p][1], bfrag[2 * p + 1][0], bfrag[2 * p + 1][1], bd);
            }
#pragma unroll
            for (int mi = 0; mi < 2; mi++)
#pragma unroll
                for (int ni = 0; ni < 8; ni++) {
                    asm volatile(
                        "mma.sync.aligned.m16n8k16.row.col.f32.f16.f16.f32 "
                        "{%0,%1,%2,%3}, {%4,%5,%6,%7}, {%8,%9}, {%0,%1,%2,%3};\n"
                        : "+f"(acc[mi][ni][0]), "+f"(acc[mi][ni][1]),
                          "+f"(acc[mi][ni][2]), "+f"(acc[mi][ni][3])
                        : "r"(af[mi][0]), "r"(af[mi][1]), "r"(af[mi][2]), "r"(af[mi][3]),
                          "r"(bfrag[ni][0]), "r"(bfrag[ni][1]));
                }
        }
    }
#undef ISSUE

#pragma unroll
    for (int mi = 0; mi < 2; mi++) {
        int r = m0 + wm + mi * 16;
#pragma unroll
        for (int ni = 0; ni < 8; ni++) {
            int c = n0 + wn + ni * 8 + 2 * t4;
            if (r + g < M) {
                __half2 v0 = __floats2half2_rn(acc[mi][ni][0], acc[mi][ni][1]);
                *(__half2*)(C + (size_t)(r + g) * Nc + c) = v0;
            }
            if (r + g + 8 < M) {
                __half2 v1 = __floats2half2_rn(acc[mi][ni][2], acc[mi][ni][3]);
                *(__half2*)(C + (size_t)(r + g + 8) * Nc + c) = v1;
            }
        }
    }

    if (asrc) {
#pragma unroll
        for (int mi = 0; mi < 2; mi++) {
            float s0 = 0.f, s1 = 0.f, d0 = 0.f, d1 = 0.f;
#pragma unroll
            for (int ni = 0; ni < 8; ni++) {
#pragma unroll
                for (int j = 0; j < 2; j++) {
                    int c = n0 + wn + ni * 8 + 2 * t4 + j;
                    float a_s = asrc[c], a_d = adst[c];
                    s0 += acc[mi][ni][j] * a_s;
                    d0 += acc[mi][ni][j] * a_d;
                    s1 += acc[mi][ni][j + 2] * a_s;
                    d1 += acc[mi][ni][j + 2] * a_d;
                }
            }
#pragma unroll
            for (int o = 1; o < 4; o <<= 1) {
                s0 += __shfl_xor_sync(0xffffffffu, s0, o);
                s1 += __shfl_xor_sync(0xffffffffu, s1, o);
                d0 += __shfl_xor_sync(0xffffffffu, d0, o);
                d1 += __shfl_xor_sync(0xffffffffu, d1, o);
            }
            if (t4 == 0) {
                int r0w = m0 + wm + mi * 16 + g;
                int r1w = r0w + 8;
                if (heads == 8) {
                    int head = (n0 + wn) >> 6;
                    if (r0w < M) { oas[r0w * 8 + head] = s0; oad[r0w * 8 + head] = d0; }
                    if (r1w < M) { oas[r1w * 8 + head] = s1; oad[r1w * 8 + head] = d1; }
                } else {
                    if (r0w < M) { atomicAdd(&oas[r0w], s0); atomicAdd(&oad[r0w], d0); }
                    if (r1w < M) { atomicAdd(&oas[r1w], s1); atomicAdd(&oad[r1w], d1); }
                }
            }
        }
    }
}

// ---------------- layer1 aggregation (node range [nbase, nbase+grid)) ----------------
__global__ void agg1_kernel(const float* __restrict__ bias, int nbase) {
    int n = blockIdx.x + nbase;
    int tid = threadIdx.x;
    int beg = g_offs[n], end = g_offs[n + 1];
    int deg = end - beg;

    __shared__ float s_ad[8];
    __shared__ float s_max[8];
    __shared__ float s_inv[8];
    __shared__ int   s_src[CAP1];
    __shared__ float s_alpha[CAP1][9];
    __shared__ unsigned s_maxi[8];
    __shared__ float s_sum8[8];

    if (tid < 8) {
        s_ad[tid] = g_ad1[n * 8 + tid];
        s_maxi[tid] = 0x007FFFFFu;
        s_sum8[tid] = 0.f;
    }
    __syncthreads();

    int c = 2 * tid;
    int hch = c >> 6;
    float accx = 0.f, accy = 0.f;

    if (deg <= CAP1) {
        for (int base = 0; base < deg; base += 32) {
            int el = base + (tid >> 3), hh = tid & 7;
            if (el < deg) {
                int s = g_csr[beg + el];
                if (hh == 0) s_src[el] = s;
                s_alpha[el][hh] = lrelu(g_as1[s * 8 + hh] + s_ad[hh]);
            }
        }
        __syncthreads();
        {
            int h = tid >> 5, l = tid & 31;
            float m = -INFINITY;
            for (int e = l; e < deg; e += 32) m = fmaxf(m, s_alpha[e][h]);
            m = warp_max(m);
            float ssum = 0.f;
            for (int e = l; e < deg; e += 32) {
                float ex = __expf(s_alpha[e][h] - m);
                s_alpha[e][h] = ex;
                ssum += ex;
            }
            ssum = warp_sum(ssum);
            if (l == 0) s_inv[h] = 1.f / (ssum + 1e-16f);
        }
        __syncthreads();
        int e = 0;
        for (; e + 8 <= deg; e += 8) {
            float2 v0 = __half22float2(__ldcg((const __half2*)(g_h1 + (size_t)s_src[e + 0] * HID1 + c)));
            float2 v1 = __half22float2(__ldcg((const __half2*)(g_h1 + (size_t)s_src[e + 1] * HID1 + c)));
            float2 v2 = __half22float2(__ldcg((const __half2*)(g_h1 + (size_t)s_src[e + 2] * HID1 + c)));
            float2 v3 = __half22float2(__ldcg((const __half2*)(g_h1 + (size_t)s_src[e + 3] * HID1 + c)));
            float2 v4 = __half22float2(__ldcg((const __half2*)(g_h1 + (size_t)s_src[e + 4] * HID1 + c)));
            float2 v5 = __half22float2(__ldcg((const __half2*)(g_h1 + (size_t)s_src[e + 5] * HID1 + c)));
            float2 v6 = __half22float2(__ldcg((const __half2*)(g_h1 + (size_t)s_src[e + 6] * HID1 + c)));
            float2 v7 = __half22float2(__ldcg((const __half2*)(g_h1 + (size_t)s_src[e + 7] * HID1 + c)));
            float k0 = s_alpha[e + 0][hch], k1 = s_alpha[e + 1][hch];
            float k2 = s_alpha[e + 2][hch], k3 = s_alpha[e + 3][hch];
            float k4 = s_alpha[e + 4][hch], k5 = s_alpha[e + 5][hch];
            float k6 = s_alpha[e + 6][hch], k7 = s_alpha[e + 7][hch];
            accx += v0.x * k0 + v1.x * k1 + v2.x * k2 + v3.x * k3
                  + v4.x * k4 + v5.x * k5 + v6.x * k6 + v7.x * k7;
            accy += v0.y * k0 + v1.y * k1 + v2.y * k2 + v3.y * k3
                  + v4.y * k4 + v5.y * k5 + v6.y * k6 + v7.y * k7;
        }
        for (; e + 4 <= deg; e += 4) {
            float2 v0 = __half22float2(__ldcg((const __half2*)(g_h1 + (size_t)s_src[e + 0] * HID1 + c)));
            float2 v1 = __half22float2(__ldcg((const __half2*)(g_h1 + (size_t)s_src[e + 1] * HID1 + c)));
            float2 v2 = __half22float2(__ldcg((const __half2*)(g_h1 + (size_t)s_src[e + 2] * HID1 + c)));
            float2 v3 = __half22float2(__ldcg((const __half2*)(g_h1 + (size_t)s_src[e + 3] * HID1 + c)));
            float k0 = s_alpha[e + 0][hch], k1 = s_alpha[e + 1][hch];
            float k2 = s_alpha[e + 2][hch], k3 = s_alpha[e + 3][hch];
            accx += v0.x * k0 + v1.x * k1 + v2.x * k2 + v3.x * k3;
            accy += v0.y * k0 + v1.y * k1 + v2.y * k2 + v3.y * k3;
        }
        for (; e < deg; e++) {
            float2 v = __half22float2(__ldcg((const __half2*)(g_h1 + (size_t)s_src[e] * HID1 + c)));
            float kc = s_alpha[e][hch];
            accx += v.x * kc;
            accy += v.y * kc;
        }
        float inv = s_inv[hch];
        accx *= inv;
        accy *= inv;
    } else {
        const float4* as4 = (const float4*)g_as1;
        float lmax[8];
#pragma unroll
        for (int h = 0; h < 8; h++) lmax[h] = -INFINITY;
        for (int e = beg + tid; e < end; e += 256) {
            int s = g_csr[e];
            float4 lo = as4[s * 2], hi = as4[s * 2 + 1];
            float av[8] = {lo.x, lo.y, lo.z, lo.w, hi.x, hi.y, hi.z, hi.w};
#pragma unroll
            for (int h = 0; h < 8; h++) lmax[h] = fmaxf(lmax[h], lrelu(av[h] + s_ad[h]));
        }
#pragma unroll
        for (int h = 0; h < 8; h++) atomicMax(&s_maxi[h], fenc(lmax[h]));
        __syncthreads();
        if (tid < 8) s_max[tid] = fdec(s_maxi[tid]);
        __syncthreads();
        float lsum[8];
#pragma unroll
        for (int h = 0; h < 8; h++) lsum[h] = 0.f;
        for (int e = beg + tid; e < end; e += 256) {
            int s = g_csr[e];
            float4 lo = as4[s * 2], hi = as4[s * 2 + 1];
            float av[8] = {lo.x, lo.y, lo.z, lo.w, hi.x, hi.y, hi.z, hi.w};
#pragma unroll
            for (int h = 0; h < 8; h++) lsum[h] += __expf(lrelu(av[h] + s_ad[h]) - s_max[h]);
        }
#pragma unroll
        for (int h = 0; h < 8; h++) atomicAdd(&s_sum8[h], lsum[h]);
        __syncthreads();
        if (tid < 8) s_inv[tid] = 1.f / (s_sum8[tid] + 1e-16f);
        __syncthreads();
        for (int cb = beg; cb < end; cb += 32) {
            int cn = end - cb; if (cn > 32) cn = 32;
            int el = tid >> 3, hh = tid & 7;
            if (el < cn) {
                int s = g_csr[cb + el];
                float a = lrelu(g_as1[s * 8 + hh] + s_ad[hh]);
                s_alpha[el][hh] = __expf(a - s_max[hh]) * s_inv[hh];
                if (hh == 0) s_src[el] = s;
            }
            __syncthreads();
            for (int e = 0; e < cn; e++) {
                float2 v = __half22float2(__ldcg((const __half2*)(g_h1 + (size_t)s_src[e] * HID1 + c)));
                float kc = s_alpha[e][hch];
                accx += v.x * kc;
                accy += v.y * kc;
            }
            __syncthreads();
        }
    }

    float2 bv = *(const float2*)(bias + c);
    float ox = accx + bv.x, oy = accy + bv.y;
    ox = ox > 0.f ? ox : expm1f(ox);
    oy = oy > 0.f ? oy : expm1f(oy);
    __half hx = __float2half(ox), hy = __float2half(oy);
    *(ushort2*)(g_o1s + (size_t)n * KDIM + c) =
        make_ushort2(*(unsigned short*)&hx, *(unsigned short*)&hy);
}

// ---------------- layer2 aggregation ----------------
__global__ void agg2_kernel(const float* __restrict__ bias, float* __restrict__ out) {
    int n = blockIdx.x;
    int tid = threadIdx.x;
    int beg = g_offs[n], end = g_offs[n + 1];
    int deg = end - beg;

    __shared__ float s_ad;
    __shared__ float s_max;
    __shared__ float s_inv;
    __shared__ unsigned s_maxi;
    __shared__ float s_sum1;
    __shared__ int   s_src[CAP2];
    __shared__ float s_alpha[CAP2];
    __shared__ float shm[8];
    __shared__ float shs[8];

    if (tid == 0) {
        s_ad = g_ad2[n];
        s_maxi = 0x007FFFFFu;
        s_sum1 = 0.f;
    }
    __syncthreads();

    float acc = 0.f;
    bool fast = (deg <= CAP2);

    if (fast) {
        if (tid < deg) {
            int s = g_csr[beg + tid];
            s_src[tid] = s;
            s_alpha[tid] = lrelu(g_as2[s] + s_ad);
        }
        __syncthreads();
        if (tid < 32) {
            float m = -INFINITY;
            for (int e = tid; e < deg; e += 32) m = fmaxf(m, s_alpha[e]);
            m = warp_max(m);
            float ssum = 0.f;
            for (int e = tid; e < deg; e += 32) {
                float ex = __expf(s_alpha[e] - m);
                s_alpha[e] = ex;
                ssum += ex;
            }
            ssum = warp_sum(ssum);
            if (tid == 0) s_inv = 1.f / (ssum + 1e-16f);
        }
        __syncthreads();
        int e = 0;
        for (; e + 8 <= deg; e += 8) {
            float v0 = __half2float(__ldcg(g_h2 + (size_t)s_src[e + 0] * OUTC + tid));
            float v1 = __half2float(__ldcg(g_h2 + (size_t)s_src[e + 1] * OUTC + tid));
            float v2 = __half2float(__ldcg(g_h2 + (size_t)s_src[e + 2] * OUTC + tid));
            float v3 = __half2float(__ldcg(g_h2 + (size_t)s_src[e + 3] * OUTC + tid));
            float v4 = __half2float(__ldcg(g_h2 + (size_t)s_src[e + 4] * OUTC + tid));
            float v5 = __half2float(__ldcg(g_h2 + (size_t)s_src[e + 5] * OUTC + tid));
            float v6 = __half2float(__ldcg(g_h2 + (size_t)s_src[e + 6] * OUTC + tid));
            float v7 = __half2float(__ldcg(g_h2 + (size_t)s_src[e + 7] * OUTC + tid));
            acc += v0 * s_alpha[e + 0] + v1 * s_alpha[e + 1] + v2 * s_alpha[e + 2] + v3 * s_alpha[e + 3]
                 + v4 * s_alpha[e + 4] + v5 * s_alpha[e + 5] + v6 * s_alpha[e + 6] + v7 * s_alpha[e + 7];
        }
        for (; e + 4 <= deg; e += 4) {
            float v0 = __half2float(__ldcg(g_h2 + (size_t)s_src[e + 0] * OUTC + tid));
            float v1 = __half2float(__ldcg(g_h2 + (size_t)s_src[e + 1] * OUTC + tid));
            float v2 = __half2float(__ldcg(g_h2 + (size_t)s_src[e + 2] * OUTC + tid));
            float v3 = __half2float(__ldcg(g_h2 + (size_t)s_src[e + 3] * OUTC + tid));
            acc += v0 * s_alpha[e + 0] + v1 * s_alpha[e + 1] + v2 * s_alpha[e + 2] + v3 * s_alpha[e + 3];
        }
        for (; e < deg; e++) acc += __half2float(__ldcg(g_h2 + (size_t)s_src[e] * OUTC + tid)) * s_alpha[e];
        acc *= s_inv;
    } else {
        float lmax = -INFINITY;
        for (int e = beg + tid; e < end; e += 256) {
            float a = lrelu(g_as2[g_csr[e]] + s_ad);
            lmax = fmaxf(lmax, a);
        }
        atomicMax(&s_maxi, fenc(lmax));
        __syncthreads();
        if (tid == 0) s_max = fdec(s_maxi);
        __syncthreads();
        float lsum = 0.f;
        for (int e = beg + tid; e < end; e += 256) {
            float a = lrelu(g_as2[g_csr[e]] + s_ad);
            lsum += __expf(a - s_max);
        }
        atomicAdd(&s_sum1, lsum);
        __syncthreads();
        if (tid == 0) s_inv = 1.f / (s_sum1 + 1e-16f);
        __syncthreads();
        for (int cb = beg; cb < end; cb += CAP2) {
            int cn = end - cb; if (cn > CAP2) cn = CAP2;
            if (tid < cn) {
                int s = g_csr[cb + tid];
                float a = lrelu(g_as2[s] + s_ad);
                s_alpha[tid] = __expf(a - s_max) * s_inv;
                s_src[tid] = s;
            }
            __syncthreads();
            for (int e = 0; e < cn; e++)
                acc += __half2float(__ldcg(g_h2 + (size_t)s_src[e] * OUTC + tid)) * s_alpha[e];
            __syncthreads();
        }
    }

    float v = acc + bias[tid];
    float wm = warp_max(v);
    if ((tid & 31) == 0) shm[tid >> 5] = wm;
    __syncthreads();
    float m = shm[0];
#pragma unroll
    for (int i = 1; i < 8; i++) m = fmaxf(m, shm[i]);
    float ex = __expf(v - m);
    float ws = warp_sum(ex);
    if ((tid & 31) == 0) shs[tid >> 5] = ws;
    __syncthreads();
    float s = 0.f;
#pragma unroll
    for (int i = 0; i < 8; i++) s += shs[i];
    out[(size_t)n * OUTC + tid] = v - m - __logf(s);
}

// ---------------- launch: fork CSR + pipelined agg1/GEMM2 tail ----------------
extern "C" void kernel_launch(void* const* d_in, const int* in_sizes, int n_in,
                              void* d_out, int out_size) {
    const float* x    = (const float*)d_in[0];
    const int*   ei   = (const int*)d_in[1];
    const float* W1   = (const float*)d_in[2];
    const float* as1  = (const float*)d_in[3];
    const float* ad1  = (const float*)d_in[4];
    const float* b1   = (const float*)d_in[5];
    const float* W2   = (const float*)d_in[6];
    const float* as2  = (const float*)d_in[7];
    const float* ad2  = (const float*)d_in[8];
    const float* b2   = (const float*)d_in[9];
    float* out = (float*)d_out;

    float *p_as1, *p_ad1, *p_as2, *p_ad2;
    __half *p_h1, *p_h2, *p_xs, *p_o1s, *p_w1t, *p_w2t;
    cudaGetSymbolAddress((void**)&p_h1, g_h1);
    cudaGetSymbolAddress((void**)&p_h2, g_h2);
    cudaGetSymbolAddress((void**)&p_as1, g_as1);
    cudaGetSymbolAddress((void**)&p_ad1, g_ad1);
    cudaGetSymbolAddress((void**)&p_as2, g_as2);
    cudaGetSymbolAddress((void**)&p_ad2, g_ad2);
    cudaGetSymbolAddress((void**)&p_xs, g_xs);
    cudaGetSymbolAddress((void**)&p_o1s, g_o1s);
    cudaGetSymbolAddress((void**)&p_w1t, g_w1t);
    cudaGetSymbolAddress((void**)&p_w2t, g_w2t);

    cudaFuncSetAttribute(mma_gemm_kernel,
                         cudaFuncAttributeMaxDynamicSharedMemorySize, GEMM_SMEM);

    static cudaStream_t s_side = nullptr;
    static cudaEvent_t ev_root = nullptr, ev_csr = nullptr, ev_a = nullptr, ev_g2a = nullptr;
    if (!s_side) {
        cudaStreamCreateWithFlags(&s_side, cudaStreamNonBlocking);
        cudaEventCreateWithFlags(&ev_root, cudaEventDisableTiming);
        cudaEventCreateWithFlags(&ev_csr, cudaEventDisableTiming);
        cudaEventCreateWithFlags(&ev_a, cudaEventDisableTiming);
        cudaEventCreateWithFlags(&ev_g2a, cudaEventDisableTiming);
    }

    // fork FIRST: side chain starts at graph t=0
    cudaEventRecord(ev_root, 0);
    cudaStreamWaitEvent(s_side, ev_root, 0);
    deg_kernel<<<(NTOT + 255) / 256, 256, 0, s_side>>>(ei);
    scan_kernel<<<1, 1024, 0, s_side>>>();
    scatter_kernel<<<(NTOT + 255) / 256, 256, 0, s_side>>>(ei);
    conv_w2_kernel<<<(KDIM * OUTC + 255) / 256, 256, 0, s_side>>>(W2, p_w2t);
    cudaEventRecord(ev_csr, s_side);

    // main stream: act+W1 convert, then GEMM1 (overlaps CSR chain)
    conv_actw1_kernel<<<(NN * (KDIM / 4) + 255) / 256, 256>>>(x, p_xs, W1, p_w1t);
    mma_gemm_kernel<<<dim3(HID1 / BN, (NN + BM - 1) / BM), 256, GEMM_SMEM>>>(
        p_xs, p_w1t, p_h1, NN, HID1, KDIM, as1, ad1, p_as1, p_ad1, 8);

    // join CSR, then first half of agg1
    cudaStreamWaitEvent(0, ev_csr, 0);
    agg1_kernel<<<SPLIT, 256>>>(b1, 0);
    cudaEventRecord(ev_a, 0);

    // side: GEMM2 on rows [0, SPLIT) while main runs agg1 second half
    cudaStreamWaitEvent(s_side, ev_a, 0);
    mma_gemm_kernel<<<dim3(OUTC / BN, SPLIT / BM), 256, GEMM_SMEM, s_side>>>(
        p_o1s, p_w2t, p_h2, SPLIT, OUTC, KDIM, as2, ad2, p_as2, p_ad2, 1);
    cudaEventRecord(ev_g2a, s_side);

    // main: agg1 second half, then GEMM2 on rows [SPLIT, NN)
    agg1_kernel<<<NN - SPLIT, 256>>>(b1, SPLIT);
    mma_gemm_kernel<<<dim3(OUTC / BN, (NN - SPLIT + BM - 1) / BM), 256, GEMM_SMEM>>>(
        p_o1s + (size_t)SPLIT * KDIM, p_w2t, p_h2 + (size_t)SPLIT * OUTC,
        NN - SPLIT, OUTC, KDIM, as2, ad2, p_as2 + SPLIT, p_ad2 + SPLIT, 1);

    // join both GEMM2 halves, then agg2
    cudaStreamWaitEvent(0, ev_g2a, 0);
    agg2_kernel<<<NN, 256>>>(b2, out);
}